// round 1
// baseline (speedup 1.0000x reference)
#include <cuda_runtime.h>
#include <math.h>

// ---------------------------------------------------------------------------
// Problem constants (fixed shapes)
// ---------------------------------------------------------------------------
#define D_MODEL 1024
#define NHEAD   16
#define HDIM    64
#define FFDIM   4096
#define BATCH   2
#define SEQ     2048
#define MROWS   (BATCH * SEQ)   // 4096

// ---------------------------------------------------------------------------
// Scratch (device globals; no allocation allowed)
// ---------------------------------------------------------------------------
__device__ float g_q  [MROWS * D_MODEL];
__device__ float g_k  [MROWS * D_MODEL];
__device__ float g_v  [MROWS * D_MODEL];
__device__ float g_ctx[MROWS * D_MODEL];
__device__ float g_t  [MROWS * D_MODEL];
__device__ float g_x1 [MROWS * D_MODEL];
__device__ float g_h  [MROWS * FFDIM];

// ---------------------------------------------------------------------------
// Tiled fp32 GEMM: C[M,N] = A[M,K] @ W[K,N] + bias (+ epilogue)
//   EPI 0: + bias
//   EPI 1: + bias + residual
//   EPI 2: gelu(x @ W + bias)   (exact gelu, erf-based)
// BM=BN=128, BK=16, 256 threads, 8x8 per thread.
// Requires M%128==0, N%128==0, K%16==0 (true for all shapes here).
// ---------------------------------------------------------------------------
#define GBM 128
#define GBN 128
#define GBK 16

template <int EPI>
__global__ void __launch_bounds__(256)
gemm_kernel(const float* __restrict__ A, const float* __restrict__ W,
            const float* __restrict__ bias, const float* __restrict__ res,
            float* __restrict__ C, int M, int N, int K)
{
    __shared__ float As[GBK][GBM];
    __shared__ float Bs[GBK][GBN];

    const int tid = threadIdx.x;
    const int tr  = tid >> 4;      // 0..15 : row group (8 rows each)
    const int tc  = tid & 15;      // 0..15 : col group (8 cols each)
    const int bm  = blockIdx.y * GBM;
    const int bn  = blockIdx.x * GBN;

    float acc[8][8];
#pragma unroll
    for (int i = 0; i < 8; i++)
#pragma unroll
        for (int j = 0; j < 8; j++) acc[i][j] = 0.0f;

    for (int k0 = 0; k0 < K; k0 += GBK) {
        // load A tile (128x16) transposed into As[16][128]
#pragma unroll
        for (int it = 0; it < 2; it++) {
            int idx = tid * 2 + it;           // 0..511
            int ar = idx >> 2;                // 0..127
            int ac = (idx & 3) * 4;           // 0,4,8,12
            float4 av = *(const float4*)(A + (size_t)(bm + ar) * K + k0 + ac);
            As[ac + 0][ar] = av.x;
            As[ac + 1][ar] = av.y;
            As[ac + 2][ar] = av.z;
            As[ac + 3][ar] = av.w;

            int br = idx >> 5;                // 0..15
            int bc = (idx & 31) * 4;          // 0..124
            *(float4*)(&Bs[br][bc]) =
                *(const float4*)(W + (size_t)(k0 + br) * N + bn + bc);
        }
        __syncthreads();

#pragma unroll
        for (int kk = 0; kk < GBK; kk++) {
            float a[8], b[8];
#pragma unroll
            for (int i = 0; i < 8; i++) a[i] = As[kk][tr * 8 + i];
#pragma unroll
            for (int j = 0; j < 8; j++) b[j] = Bs[kk][tc * 8 + j];
#pragma unroll
            for (int i = 0; i < 8; i++)
#pragma unroll
                for (int j = 0; j < 8; j++)
                    acc[i][j] = fmaf(a[i], b[j], acc[i][j]);
        }
        __syncthreads();
    }

    // epilogue
#pragma unroll
    for (int i = 0; i < 8; i++) {
        const int r = bm + tr * 8 + i;
#pragma unroll
        for (int j = 0; j < 8; j += 4) {
            const int c = bn + tc * 8 + j;
            float4 v;
            v.x = acc[i][j + 0] + bias[c + 0];
            v.y = acc[i][j + 1] + bias[c + 1];
            v.z = acc[i][j + 2] + bias[c + 2];
            v.w = acc[i][j + 3] + bias[c + 3];
            if (EPI == 1) {
                float4 rv = *(const float4*)(res + (size_t)r * N + c);
                v.x += rv.x; v.y += rv.y; v.z += rv.z; v.w += rv.w;
            }
            if (EPI == 2) {
                v.x = 0.5f * v.x * (1.0f + erff(v.x * 0.70710678118654752f));
                v.y = 0.5f * v.y * (1.0f + erff(v.y * 0.70710678118654752f));
                v.z = 0.5f * v.z * (1.0f + erff(v.z * 0.70710678118654752f));
                v.w = 0.5f * v.w * (1.0f + erff(v.w * 0.70710678118654752f));
            }
            *(float4*)(C + (size_t)r * N + c) = v;
        }
    }
}

// ---------------------------------------------------------------------------
// Flash-attention (fp32), BQ=64, BK=64, HD=64.
// grid: (SEQ/64, BATCH*NHEAD), 256 threads.
// q,k,v are stored [MROWS, D_MODEL] (head slice contiguous).
// ---------------------------------------------------------------------------
#define ATP 65   // padded row stride in smem

__global__ void __launch_bounds__(256)
attn_kernel(const float* __restrict__ q, const float* __restrict__ k,
            const float* __restrict__ v, const int* __restrict__ mask,
            float* __restrict__ ctx)
{
    extern __shared__ float sm[];
    float* Qs = sm;                 // 64 x 65
    float* Ks = Qs + 64 * ATP;      // 64 x 65
    float* Vs = Ks + 64 * ATP;      // 64 x 65
    float* Ps = Vs + 64 * ATP;      // 64 x 65
    int*   Ms = (int*)(Ps + 64 * ATP); // 64

    const int tid = threadIdx.x;
    const int tr  = tid >> 4;   // 0..15 -> rows tr*4..tr*4+3
    const int tc  = tid & 15;   // 0..15 -> cols tc*4..tc*4+3
    const int bh  = blockIdx.y;
    const int b   = bh >> 4;
    const int h   = bh & 15;
    const int m0  = b * SEQ + blockIdx.x * 64;
    const size_t colh = (size_t)h * HDIM;

    // load Q tile, pre-scaled by 1/sqrt(HD)
    for (int i = tid; i < 64 * 16; i += 256) {
        int r = i >> 4, c4 = (i & 15) * 4;
        float4 val = *(const float4*)(q + (size_t)(m0 + r) * D_MODEL + colh + c4);
        Qs[r * ATP + c4 + 0] = val.x * 0.125f;
        Qs[r * ATP + c4 + 1] = val.y * 0.125f;
        Qs[r * ATP + c4 + 2] = val.z * 0.125f;
        Qs[r * ATP + c4 + 3] = val.w * 0.125f;
    }

    float m_i[4], l_i[4], o[4][4];
#pragma unroll
    for (int ii = 0; ii < 4; ii++) {
        m_i[ii] = -3.0e38f;
        l_i[ii] = 0.0f;
#pragma unroll
        for (int cc = 0; cc < 4; cc++) o[ii][cc] = 0.0f;
    }

    for (int kt = 0; kt < SEQ / 64; kt++) {
        const int n0 = b * SEQ + kt * 64;
        __syncthreads();   // guard Ks/Vs/Ps reuse from previous iteration
        for (int i = tid; i < 64 * 16; i += 256) {
            int r = i >> 4, c4 = (i & 15) * 4;
            float4 kv4 = *(const float4*)(k + (size_t)(n0 + r) * D_MODEL + colh + c4);
            Ks[r * ATP + c4 + 0] = kv4.x;
            Ks[r * ATP + c4 + 1] = kv4.y;
            Ks[r * ATP + c4 + 2] = kv4.z;
            Ks[r * ATP + c4 + 3] = kv4.w;
            float4 vv4 = *(const float4*)(v + (size_t)(n0 + r) * D_MODEL + colh + c4);
            Vs[r * ATP + c4 + 0] = vv4.x;
            Vs[r * ATP + c4 + 1] = vv4.y;
            Vs[r * ATP + c4 + 2] = vv4.z;
            Vs[r * ATP + c4 + 3] = vv4.w;
        }
        if (tid < 64) Ms[tid] = mask[b * SEQ + kt * 64 + tid];
        __syncthreads();

        // scores: s = Qs @ Ks^T (Q already scaled)
        float s[4][4];
#pragma unroll
        for (int ii = 0; ii < 4; ii++)
#pragma unroll
            for (int jj = 0; jj < 4; jj++) s[ii][jj] = 0.0f;

        for (int d = 0; d < 64; d++) {
            float qv[4], kv[4];
#pragma unroll
            for (int ii = 0; ii < 4; ii++) qv[ii] = Qs[(tr * 4 + ii) * ATP + d];
#pragma unroll
            for (int jj = 0; jj < 4; jj++) kv[jj] = Ks[(tc * 4 + jj) * ATP + d];
#pragma unroll
            for (int ii = 0; ii < 4; ii++)
#pragma unroll
                for (int jj = 0; jj < 4; jj++)
                    s[ii][jj] = fmaf(qv[ii], kv[jj], s[ii][jj]);
        }

        // mask (replace with -1e9 where mask==0, matching reference)
#pragma unroll
        for (int jj = 0; jj < 4; jj++) {
            if (Ms[tc * 4 + jj] == 0) {
#pragma unroll
                for (int ii = 0; ii < 4; ii++) s[ii][jj] = -1e9f;
            }
        }

        // online softmax update
#pragma unroll
        for (int ii = 0; ii < 4; ii++) {
            float tm = fmaxf(fmaxf(s[ii][0], s[ii][1]), fmaxf(s[ii][2], s[ii][3]));
#pragma unroll
            for (int off = 8; off > 0; off >>= 1)
                tm = fmaxf(tm, __shfl_xor_sync(0xffffffffu, tm, off));
            float nm   = fmaxf(m_i[ii], tm);
            float corr = __expf(m_i[ii] - nm);
            m_i[ii] = nm;
            float rs = 0.0f;
#pragma unroll
            for (int jj = 0; jj < 4; jj++) {
                float p = __expf(s[ii][jj] - nm);
                s[ii][jj] = p;
                rs += p;
            }
#pragma unroll
            for (int off = 8; off > 0; off >>= 1)
                rs += __shfl_xor_sync(0xffffffffu, rs, off);
            l_i[ii] = l_i[ii] * corr + rs;
#pragma unroll
            for (int cc = 0; cc < 4; cc++) o[ii][cc] *= corr;
#pragma unroll
            for (int jj = 0; jj < 4; jj++)
                Ps[(tr * 4 + ii) * ATP + tc * 4 + jj] = s[ii][jj];
        }
        __syncthreads();

        // o += P @ V
        for (int j = 0; j < 64; j++) {
            float pv[4], vv[4];
#pragma unroll
            for (int ii = 0; ii < 4; ii++) pv[ii] = Ps[(tr * 4 + ii) * ATP + j];
#pragma unroll
            for (int cc = 0; cc < 4; cc++) vv[cc] = Vs[j * ATP + tc * 4 + cc];
#pragma unroll
            for (int ii = 0; ii < 4; ii++)
#pragma unroll
                for (int cc = 0; cc < 4; cc++)
                    o[ii][cc] = fmaf(pv[ii], vv[cc], o[ii][cc]);
        }
    }

    // write ctx
#pragma unroll
    for (int ii = 0; ii < 4; ii++) {
        float inv = 1.0f / l_i[ii];
#pragma unroll
        for (int cc = 0; cc < 4; cc++)
            ctx[(size_t)(m0 + tr * 4 + ii) * D_MODEL + colh + tc * 4 + cc] =
                o[ii][cc] * inv;
    }
}

// ---------------------------------------------------------------------------
// LayerNorm helpers
// ---------------------------------------------------------------------------
__device__ __forceinline__ float block_reduce_sum(float val, float* red)
{
#pragma unroll
    for (int o = 16; o > 0; o >>= 1)
        val += __shfl_xor_sync(0xffffffffu, val, o);
    int warp = threadIdx.x >> 5;
    if ((threadIdx.x & 31) == 0) red[warp] = val;
    __syncthreads();
    if (threadIdx.x < 32) {
        float v = (threadIdx.x < 8) ? red[threadIdx.x] : 0.0f;
#pragma unroll
        for (int o = 4; o > 0; o >>= 1)
            v += __shfl_xor_sync(0xffffffffu, v, o);
        if (threadIdx.x == 0) red[0] = v;
    }
    __syncthreads();
    float r = red[0];
    __syncthreads();
    return r;
}

// out = LN(in) ; one block per row (D=1024, 256 threads, 4 elems/thread)
__global__ void __launch_bounds__(256)
ln_kernel(const float* __restrict__ in, const float* __restrict__ g,
          const float* __restrict__ bb, float eps, float* __restrict__ out)
{
    __shared__ float red[8];
    const int row = blockIdx.x;
    const float* rp = in + (size_t)row * D_MODEL;
    float vloc[4];
    float s = 0.0f;
#pragma unroll
    for (int i = 0; i < 4; i++) {
        vloc[i] = rp[threadIdx.x + i * 256];
        s += vloc[i];
    }
    float mean = block_reduce_sum(s, red) * (1.0f / D_MODEL);
    float vs = 0.0f;
#pragma unroll
    for (int i = 0; i < 4; i++) {
        float dv = vloc[i] - mean;
        vs += dv * dv;
    }
    float var  = block_reduce_sum(vs, red) * (1.0f / D_MODEL);
    float rstd = rsqrtf(var + eps);
#pragma unroll
    for (int i = 0; i < 4; i++) {
        int c = threadIdx.x + i * 256;
        out[(size_t)row * D_MODEL + c] = (vloc[i] - mean) * rstd * g[c] + bb[c];
    }
}

// fused: ff = LN(t2, lnf, 1e-12); out = LN(x1 + ff, ln2, 1e-5)
__global__ void __launch_bounds__(256)
ln2_fuse_kernel(const float* __restrict__ t2, const float* __restrict__ x1,
                const float* __restrict__ lnf_g, const float* __restrict__ lnf_b,
                const float* __restrict__ ln2_g, const float* __restrict__ ln2_b,
                float* __restrict__ out)
{
    __shared__ float red[8];
    const int row = blockIdx.x;
    const float* tp = t2 + (size_t)row * D_MODEL;
    const float* xp = x1 + (size_t)row * D_MODEL;
    float tv[4], xv[4];
    float s = 0.0f;
#pragma unroll
    for (int i = 0; i < 4; i++) {
        int c = threadIdx.x + i * 256;
        tv[i] = tp[c];
        xv[i] = xp[c];
        s += tv[i];
    }
    float mean1 = block_reduce_sum(s, red) * (1.0f / D_MODEL);
    float vs = 0.0f;
#pragma unroll
    for (int i = 0; i < 4; i++) {
        float dv = tv[i] - mean1;
        vs += dv * dv;
    }
    float var1  = block_reduce_sum(vs, red) * (1.0f / D_MODEL);
    float rstd1 = rsqrtf(var1 + 1e-12f);

    float u[4];
    float s2 = 0.0f;
#pragma unroll
    for (int i = 0; i < 4; i++) {
        int c = threadIdx.x + i * 256;
        float ff = (tv[i] - mean1) * rstd1 * lnf_g[c] + lnf_b[c];
        u[i] = xv[i] + ff;
        s2 += u[i];
    }
    float mean2 = block_reduce_sum(s2, red) * (1.0f / D_MODEL);
    float vs2 = 0.0f;
#pragma unroll
    for (int i = 0; i < 4; i++) {
        float dv = u[i] - mean2;
        vs2 += dv * dv;
    }
    float var2  = block_reduce_sum(vs2, red) * (1.0f / D_MODEL);
    float rstd2 = rsqrtf(var2 + 1e-5f);
#pragma unroll
    for (int i = 0; i < 4; i++) {
        int c = threadIdx.x + i * 256;
        out[(size_t)row * D_MODEL + c] = (u[i] - mean2) * rstd2 * ln2_g[c] + ln2_b[c];
    }
}

// ---------------------------------------------------------------------------
// Launcher
// ---------------------------------------------------------------------------
extern "C" void kernel_launch(void* const* d_in, const int* in_sizes, int n_in,
                              void* d_out, int out_size)
{
    const float* x      = (const float*)d_in[0];
    const int*   mask   = (const int*)  d_in[1];
    const float* wq     = (const float*)d_in[2];
    const float* bq     = (const float*)d_in[3];
    const float* wk     = (const float*)d_in[4];
    const float* bk     = (const float*)d_in[5];
    const float* wv     = (const float*)d_in[6];
    const float* bv     = (const float*)d_in[7];
    const float* wo     = (const float*)d_in[8];
    const float* bo     = (const float*)d_in[9];
    const float* ln1_g  = (const float*)d_in[10];
    const float* ln1_b  = (const float*)d_in[11];
    const float* w1     = (const float*)d_in[12];
    const float* b1     = (const float*)d_in[13];
    const float* w2     = (const float*)d_in[14];
    const float* b2     = (const float*)d_in[15];
    const float* lnf_g  = (const float*)d_in[16];
    const float* lnf_b  = (const float*)d_in[17];
    const float* ln2_g  = (const float*)d_in[18];
    const float* ln2_b  = (const float*)d_in[19];
    float* out = (float*)d_out;

    float *q, *k, *v, *ctx, *t, *x1, *h;
    cudaGetSymbolAddress((void**)&q,   g_q);
    cudaGetSymbolAddress((void**)&k,   g_k);
    cudaGetSymbolAddress((void**)&v,   g_v);
    cudaGetSymbolAddress((void**)&ctx, g_ctx);
    cudaGetSymbolAddress((void**)&t,   g_t);
    cudaGetSymbolAddress((void**)&x1,  g_x1);
    cudaGetSymbolAddress((void**)&h,   g_h);

    const int attn_smem = (4 * 64 * ATP) * (int)sizeof(float) + 64 * (int)sizeof(int);
    cudaFuncSetAttribute(attn_kernel,
                         cudaFuncAttributeMaxDynamicSharedMemorySize, attn_smem);

    // QKV projections
    gemm_kernel<0><<<dim3(D_MODEL / GBN, MROWS / GBM), 256>>>(
        x, wq, bq, nullptr, q, MROWS, D_MODEL, D_MODEL);
    gemm_kernel<0><<<dim3(D_MODEL / GBN, MROWS / GBM), 256>>>(
        x, wk, bk, nullptr, k, MROWS, D_MODEL, D_MODEL);
    gemm_kernel<0><<<dim3(D_MODEL / GBN, MROWS / GBM), 256>>>(
        x, wv, bv, nullptr, v, MROWS, D_MODEL, D_MODEL);

    // attention
    attn_kernel<<<dim3(SEQ / 64, BATCH * NHEAD), 256, attn_smem>>>(
        q, k, v, mask, ctx);

    // output projection + residual, then LN1
    gemm_kernel<1><<<dim3(D_MODEL / GBN, MROWS / GBM), 256>>>(
        ctx, wo, bo, x, t, MROWS, D_MODEL, D_MODEL);
    ln_kernel<<<MROWS, 256>>>(t, ln1_g, ln1_b, 1e-5f, x1);

    // FFN
    gemm_kernel<2><<<dim3(FFDIM / GBN, MROWS / GBM), 256>>>(
        x1, w1, b1, nullptr, h, MROWS, FFDIM, D_MODEL);
    gemm_kernel<1><<<dim3(D_MODEL / GBN, MROWS / GBM), 256>>>(
        h, w2, b2, x1, t, MROWS, D_MODEL, FFDIM);

    // fused double LayerNorm epilogue
    ln2_fuse_kernel<<<MROWS, 256>>>(t, x1, lnf_g, lnf_b, ln2_g, ln2_b, out);
}

// round 2
// speedup vs baseline: 1.7945x; 1.7945x over previous
#include <cuda_runtime.h>
#include <math.h>
#include <stdint.h>

// ---------------------------------------------------------------------------
// Problem constants (fixed shapes)
// ---------------------------------------------------------------------------
#define D_MODEL 1024
#define NHEAD   16
#define HDIM    64
#define FFDIM   4096
#define BATCH   2
#define SEQ     2048
#define MROWS   (BATCH * SEQ)   // 4096

// ---------------------------------------------------------------------------
// Scratch (device globals; no allocation allowed)
// ---------------------------------------------------------------------------
__device__ float g_q  [MROWS * D_MODEL];
__device__ float g_k  [MROWS * D_MODEL];
__device__ float g_v  [MROWS * D_MODEL];
__device__ float g_ctx[MROWS * D_MODEL];
__device__ float g_t  [MROWS * D_MODEL];
__device__ float g_x1 [MROWS * D_MODEL];
__device__ float g_h  [MROWS * FFDIM];

// ---------------------------------------------------------------------------
// tf32 helpers
// ---------------------------------------------------------------------------
__device__ __forceinline__ uint32_t f2tf32(float x) {
    uint32_t r;
    asm("cvt.rna.tf32.f32 %0, %1;" : "=r"(r) : "f"(x));
    return r;
}

__device__ __forceinline__ void mma_tf32(float* c, const uint32_t* a, const uint32_t* b) {
    asm volatile(
        "mma.sync.aligned.m16n8k8.row.col.f32.tf32.tf32.f32 "
        "{%0,%1,%2,%3}, {%4,%5,%6,%7}, {%8,%9}, {%0,%1,%2,%3};"
        : "+f"(c[0]), "+f"(c[1]), "+f"(c[2]), "+f"(c[3])
        : "r"(a[0]), "r"(a[1]), "r"(a[2]), "r"(a[3]), "r"(b[0]), "r"(b[1]));
}

// ---------------------------------------------------------------------------
// tf32 tensor-core GEMM: C[M,N] = A[M,K] @ W[K,N] + bias (+ epilogue)
//   EPI 0: + bias
//   EPI 1: + bias + residual
//   EPI 2: gelu(x @ W + bias)   (exact gelu, erf-based)
// CTA tile 128x128x32, 256 threads (8 warps of 64x32).
// Requires M%128==0, N%128==0, K%32==0 (true for all shapes here).
// ---------------------------------------------------------------------------
#define SA 137   // As row stride (S % 8 == 1 -> conflict-free transposing STS)
#define SB 136   // Bs row stride (8 mod 32 -> conflict-free frag LDS)

template <int EPI>
__global__ void __launch_bounds__(256, 2)
gemm_tf32_kernel(const float* __restrict__ A, const float* __restrict__ W,
                 const float* __restrict__ bias, const float* __restrict__ res,
                 float* __restrict__ C, int M, int N, int K)
{
    __shared__ uint32_t As[32 * SA];   // [k][m], tf32 bits
    __shared__ uint32_t Bs[32 * SB];   // [k][n], tf32 bits

    const int tid     = threadIdx.x;
    const int lane    = tid & 31;
    const int warp_id = tid >> 5;
    const int g       = lane >> 2;     // groupID 0..7
    const int tig     = lane & 3;      // threadID-in-group 0..3
    const int wm      = (warp_id >> 2) * 64;  // warp row offset 0/64
    const int wn      = (warp_id & 3) * 32;   // warp col offset 0..96
    const int bm      = blockIdx.y * 128;
    const int bn      = blockIdx.x * 128;

    float acc[4][4][4];   // [m-tile][n-tile][c-frag]
#pragma unroll
    for (int i = 0; i < 4; i++)
#pragma unroll
        for (int j = 0; j < 4; j++)
#pragma unroll
            for (int r = 0; r < 4; r++) acc[i][j][r] = 0.0f;

    for (int k0 = 0; k0 < K; k0 += 32) {
        // ---- load A tile 128x32 -> As[k][m] (transposed, tf32) ----
#pragma unroll
        for (int it = 0; it < 4; it++) {
            int c  = tid + it * 256;        // 0..1023
            int m  = c >> 3;                // 0..127
            int kc = (c & 7) * 4;           // 0..28
            float4 av = *(const float4*)(A + (size_t)(bm + m) * K + k0 + kc);
            As[(kc + 0) * SA + m] = f2tf32(av.x);
            As[(kc + 1) * SA + m] = f2tf32(av.y);
            As[(kc + 2) * SA + m] = f2tf32(av.z);
            As[(kc + 3) * SA + m] = f2tf32(av.w);
        }
        // ---- load B tile 32x128 -> Bs[k][n] (tf32) ----
#pragma unroll
        for (int it = 0; it < 4; it++) {
            int c  = tid + it * 256;        // 0..1023
            int kr = c >> 5;                // 0..31
            int nc = (c & 31) * 4;          // 0..124
            float4 bv = *(const float4*)(W + (size_t)(k0 + kr) * N + bn + nc);
            uint4 tv;
            tv.x = f2tf32(bv.x);
            tv.y = f2tf32(bv.y);
            tv.z = f2tf32(bv.z);
            tv.w = f2tf32(bv.w);
            *(uint4*)(&Bs[kr * SB + nc]) = tv;
        }
        __syncthreads();

        // ---- 4 k8 steps ----
#pragma unroll
        for (int ks = 0; ks < 4; ks++) {
            const int kb = ks * 8;
            uint32_t af[4][4];
#pragma unroll
            for (int mt = 0; mt < 4; mt++) {
                const int mb = wm + mt * 16 + g;
                af[mt][0] = As[(kb + tig    ) * SA + mb    ];
                af[mt][1] = As[(kb + tig    ) * SA + mb + 8];
                af[mt][2] = As[(kb + tig + 4) * SA + mb    ];
                af[mt][3] = As[(kb + tig + 4) * SA + mb + 8];
            }
            uint32_t bf[4][2];
#pragma unroll
            for (int nt = 0; nt < 4; nt++) {
                const int nb = wn + nt * 8 + g;
                bf[nt][0] = Bs[(kb + tig    ) * SB + nb];
                bf[nt][1] = Bs[(kb + tig + 4) * SB + nb];
            }
#pragma unroll
            for (int mt = 0; mt < 4; mt++)
#pragma unroll
                for (int nt = 0; nt < 4; nt++)
                    mma_tf32(acc[mt][nt], af[mt], bf[nt]);
        }
        __syncthreads();
    }

    // ---- epilogue ----
#pragma unroll
    for (int mt = 0; mt < 4; mt++) {
        const int r0 = bm + wm + mt * 16 + g;
        const int r1 = r0 + 8;
#pragma unroll
        for (int nt = 0; nt < 4; nt++) {
            const int col = bn + wn + nt * 8 + tig * 2;
            float2 bv = *(const float2*)(bias + col);
            float2 v0, v1;
            v0.x = acc[mt][nt][0] + bv.x;
            v0.y = acc[mt][nt][1] + bv.y;
            v1.x = acc[mt][nt][2] + bv.x;
            v1.y = acc[mt][nt][3] + bv.y;
            if (EPI == 1) {
                float2 ra = *(const float2*)(res + (size_t)r0 * N + col);
                float2 rb = *(const float2*)(res + (size_t)r1 * N + col);
                v0.x += ra.x; v0.y += ra.y;
                v1.x += rb.x; v1.y += rb.y;
            }
            if (EPI == 2) {
                v0.x = 0.5f * v0.x * (1.0f + erff(v0.x * 0.70710678118654752f));
                v0.y = 0.5f * v0.y * (1.0f + erff(v0.y * 0.70710678118654752f));
                v1.x = 0.5f * v1.x * (1.0f + erff(v1.x * 0.70710678118654752f));
                v1.y = 0.5f * v1.y * (1.0f + erff(v1.y * 0.70710678118654752f));
            }
            *(float2*)(C + (size_t)r0 * N + col) = v0;
            *(float2*)(C + (size_t)r1 * N + col) = v1;
        }
    }
}

// ---------------------------------------------------------------------------
// Flash-attention (fp32), BQ=64, BK=64, HD=64.  (unchanged from R1)
// ---------------------------------------------------------------------------
#define ATP 65   // padded row stride in smem

__global__ void __launch_bounds__(256)
attn_kernel(const float* __restrict__ q, const float* __restrict__ k,
            const float* __restrict__ v, const int* __restrict__ mask,
            float* __restrict__ ctx)
{
    extern __shared__ float sm[];
    float* Qs = sm;                 // 64 x 65
    float* Ks = Qs + 64 * ATP;      // 64 x 65
    float* Vs = Ks + 64 * ATP;      // 64 x 65
    float* Ps = Vs + 64 * ATP;      // 64 x 65
    int*   Ms = (int*)(Ps + 64 * ATP); // 64

    const int tid = threadIdx.x;
    const int tr  = tid >> 4;   // 0..15 -> rows tr*4..tr*4+3
    const int tc  = tid & 15;   // 0..15 -> cols tc*4..tc*4+3
    const int bh  = blockIdx.y;
    const int b   = bh >> 4;
    const int h   = bh & 15;
    const int m0  = b * SEQ + blockIdx.x * 64;
    const size_t colh = (size_t)h * HDIM;

    for (int i = tid; i < 64 * 16; i += 256) {
        int r = i >> 4, c4 = (i & 15) * 4;
        float4 val = *(const float4*)(q + (size_t)(m0 + r) * D_MODEL + colh + c4);
        Qs[r * ATP + c4 + 0] = val.x * 0.125f;
        Qs[r * ATP + c4 + 1] = val.y * 0.125f;
        Qs[r * ATP + c4 + 2] = val.z * 0.125f;
        Qs[r * ATP + c4 + 3] = val.w * 0.125f;
    }

    float m_i[4], l_i[4], o[4][4];
#pragma unroll
    for (int ii = 0; ii < 4; ii++) {
        m_i[ii] = -3.0e38f;
        l_i[ii] = 0.0f;
#pragma unroll
        for (int cc = 0; cc < 4; cc++) o[ii][cc] = 0.0f;
    }

    for (int kt = 0; kt < SEQ / 64; kt++) {
        const int n0 = b * SEQ + kt * 64;
        __syncthreads();
        for (int i = tid; i < 64 * 16; i += 256) {
            int r = i >> 4, c4 = (i & 15) * 4;
            float4 kv4 = *(const float4*)(k + (size_t)(n0 + r) * D_MODEL + colh + c4);
            Ks[r * ATP + c4 + 0] = kv4.x;
            Ks[r * ATP + c4 + 1] = kv4.y;
            Ks[r * ATP + c4 + 2] = kv4.z;
            Ks[r * ATP + c4 + 3] = kv4.w;
            float4 vv4 = *(const float4*)(v + (size_t)(n0 + r) * D_MODEL + colh + c4);
            Vs[r * ATP + c4 + 0] = vv4.x;
            Vs[r * ATP + c4 + 1] = vv4.y;
            Vs[r * ATP + c4 + 2] = vv4.z;
            Vs[r * ATP + c4 + 3] = vv4.w;
        }
        if (tid < 64) Ms[tid] = mask[b * SEQ + kt * 64 + tid];
        __syncthreads();

        float s[4][4];
#pragma unroll
        for (int ii = 0; ii < 4; ii++)
#pragma unroll
            for (int jj = 0; jj < 4; jj++) s[ii][jj] = 0.0f;

        for (int d = 0; d < 64; d++) {
            float qv[4], kv[4];
#pragma unroll
            for (int ii = 0; ii < 4; ii++) qv[ii] = Qs[(tr * 4 + ii) * ATP + d];
#pragma unroll
            for (int jj = 0; jj < 4; jj++) kv[jj] = Ks[(tc * 4 + jj) * ATP + d];
#pragma unroll
            for (int ii = 0; ii < 4; ii++)
#pragma unroll
                for (int jj = 0; jj < 4; jj++)
                    s[ii][jj] = fmaf(qv[ii], kv[jj], s[ii][jj]);
        }

#pragma unroll
        for (int jj = 0; jj < 4; jj++) {
            if (Ms[tc * 4 + jj] == 0) {
#pragma unroll
                for (int ii = 0; ii < 4; ii++) s[ii][jj] = -1e9f;
            }
        }

#pragma unroll
        for (int ii = 0; ii < 4; ii++) {
            float tm = fmaxf(fmaxf(s[ii][0], s[ii][1]), fmaxf(s[ii][2], s[ii][3]));
#pragma unroll
            for (int off = 8; off > 0; off >>= 1)
                tm = fmaxf(tm, __shfl_xor_sync(0xffffffffu, tm, off));
            float nm   = fmaxf(m_i[ii], tm);
            float corr = __expf(m_i[ii] - nm);
            m_i[ii] = nm;
            float rs = 0.0f;
#pragma unroll
            for (int jj = 0; jj < 4; jj++) {
                float p = __expf(s[ii][jj] - nm);
                s[ii][jj] = p;
                rs += p;
            }
#pragma unroll
            for (int off = 8; off > 0; off >>= 1)
                rs += __shfl_xor_sync(0xffffffffu, rs, off);
            l_i[ii] = l_i[ii] * corr + rs;
#pragma unroll
            for (int cc = 0; cc < 4; cc++) o[ii][cc] *= corr;
#pragma unroll
            for (int jj = 0; jj < 4; jj++)
                Ps[(tr * 4 + ii) * ATP + tc * 4 + jj] = s[ii][jj];
        }
        __syncthreads();

        for (int j = 0; j < 64; j++) {
            float pv[4], vv[4];
#pragma unroll
            for (int ii = 0; ii < 4; ii++) pv[ii] = Ps[(tr * 4 + ii) * ATP + j];
#pragma unroll
            for (int cc = 0; cc < 4; cc++) vv[cc] = Vs[j * ATP + tc * 4 + cc];
#pragma unroll
            for (int ii = 0; ii < 4; ii++)
#pragma unroll
                for (int cc = 0; cc < 4; cc++)
                    o[ii][cc] = fmaf(pv[ii], vv[cc], o[ii][cc]);
        }
    }

#pragma unroll
    for (int ii = 0; ii < 4; ii++) {
        float inv = 1.0f / l_i[ii];
#pragma unroll
        for (int cc = 0; cc < 4; cc++)
            ctx[(size_t)(m0 + tr * 4 + ii) * D_MODEL + colh + tc * 4 + cc] =
                o[ii][cc] * inv;
    }
}

// ---------------------------------------------------------------------------
// LayerNorm helpers (unchanged)
// ---------------------------------------------------------------------------
__device__ __forceinline__ float block_reduce_sum(float val, float* red)
{
#pragma unroll
    for (int o = 16; o > 0; o >>= 1)
        val += __shfl_xor_sync(0xffffffffu, val, o);
    int warp = threadIdx.x >> 5;
    if ((threadIdx.x & 31) == 0) red[warp] = val;
    __syncthreads();
    if (threadIdx.x < 32) {
        float v = (threadIdx.x < 8) ? red[threadIdx.x] : 0.0f;
#pragma unroll
        for (int o = 4; o > 0; o >>= 1)
            v += __shfl_xor_sync(0xffffffffu, v, o);
        if (threadIdx.x == 0) red[0] = v;
    }
    __syncthreads();
    float r = red[0];
    __syncthreads();
    return r;
}

__global__ void __launch_bounds__(256)
ln_kernel(const float* __restrict__ in, const float* __restrict__ g,
          const float* __restrict__ bb, float eps, float* __restrict__ out)
{
    __shared__ float red[8];
    const int row = blockIdx.x;
    const float* rp = in + (size_t)row * D_MODEL;
    float vloc[4];
    float s = 0.0f;
#pragma unroll
    for (int i = 0; i < 4; i++) {
        vloc[i] = rp[threadIdx.x + i * 256];
        s += vloc[i];
    }
    float mean = block_reduce_sum(s, red) * (1.0f / D_MODEL);
    float vs = 0.0f;
#pragma unroll
    for (int i = 0; i < 4; i++) {
        float dv = vloc[i] - mean;
        vs += dv * dv;
    }
    float var  = block_reduce_sum(vs, red) * (1.0f / D_MODEL);
    float rstd = rsqrtf(var + eps);
#pragma unroll
    for (int i = 0; i < 4; i++) {
        int c = threadIdx.x + i * 256;
        out[(size_t)row * D_MODEL + c] = (vloc[i] - mean) * rstd * g[c] + bb[c];
    }
}

__global__ void __launch_bounds__(256)
ln2_fuse_kernel(const float* __restrict__ t2, const float* __restrict__ x1,
                const float* __restrict__ lnf_g, const float* __restrict__ lnf_b,
                const float* __restrict__ ln2_g, const float* __restrict__ ln2_b,
                float* __restrict__ out)
{
    __shared__ float red[8];
    const int row = blockIdx.x;
    const float* tp = t2 + (size_t)row * D_MODEL;
    const float* xp = x1 + (size_t)row * D_MODEL;
    float tv[4], xv[4];
    float s = 0.0f;
#pragma unroll
    for (int i = 0; i < 4; i++) {
        int c = threadIdx.x + i * 256;
        tv[i] = tp[c];
        xv[i] = xp[c];
        s += tv[i];
    }
    float mean1 = block_reduce_sum(s, red) * (1.0f / D_MODEL);
    float vs = 0.0f;
#pragma unroll
    for (int i = 0; i < 4; i++) {
        float dv = tv[i] - mean1;
        vs += dv * dv;
    }
    float var1  = block_reduce_sum(vs, red) * (1.0f / D_MODEL);
    float rstd1 = rsqrtf(var1 + 1e-12f);

    float u[4];
    float s2 = 0.0f;
#pragma unroll
    for (int i = 0; i < 4; i++) {
        int c = threadIdx.x + i * 256;
        float ff = (tv[i] - mean1) * rstd1 * lnf_g[c] + lnf_b[c];
        u[i] = xv[i] + ff;
        s2 += u[i];
    }
    float mean2 = block_reduce_sum(s2, red) * (1.0f / D_MODEL);
    float vs2 = 0.0f;
#pragma unroll
    for (int i = 0; i < 4; i++) {
        float dv = u[i] - mean2;
        vs2 += dv * dv;
    }
    float var2  = block_reduce_sum(vs2, red) * (1.0f / D_MODEL);
    float rstd2 = rsqrtf(var2 + 1e-5f);
#pragma unroll
    for (int i = 0; i < 4; i++) {
        int c = threadIdx.x + i * 256;
        out[(size_t)row * D_MODEL + c] = (u[i] - mean2) * rstd2 * ln2_g[c] + ln2_b[c];
    }
}

// ---------------------------------------------------------------------------
// Launcher
// ---------------------------------------------------------------------------
extern "C" void kernel_launch(void* const* d_in, const int* in_sizes, int n_in,
                              void* d_out, int out_size)
{
    const float* x      = (const float*)d_in[0];
    const int*   mask   = (const int*)  d_in[1];
    const float* wq     = (const float*)d_in[2];
    const float* bq     = (const float*)d_in[3];
    const float* wk     = (const float*)d_in[4];
    const float* bk     = (const float*)d_in[5];
    const float* wv     = (const float*)d_in[6];
    const float* bv     = (const float*)d_in[7];
    const float* wo     = (const float*)d_in[8];
    const float* bo     = (const float*)d_in[9];
    const float* ln1_g  = (const float*)d_in[10];
    const float* ln1_b  = (const float*)d_in[11];
    const float* w1     = (const float*)d_in[12];
    const float* b1     = (const float*)d_in[13];
    const float* w2     = (const float*)d_in[14];
    const float* b2     = (const float*)d_in[15];
    const float* lnf_g  = (const float*)d_in[16];
    const float* lnf_b  = (const float*)d_in[17];
    const float* ln2_g  = (const float*)d_in[18];
    const float* ln2_b  = (const float*)d_in[19];
    float* out = (float*)d_out;

    float *q, *k, *v, *ctx, *t, *x1, *h;
    cudaGetSymbolAddress((void**)&q,   g_q);
    cudaGetSymbolAddress((void**)&k,   g_k);
    cudaGetSymbolAddress((void**)&v,   g_v);
    cudaGetSymbolAddress((void**)&ctx, g_ctx);
    cudaGetSymbolAddress((void**)&t,   g_t);
    cudaGetSymbolAddress((void**)&x1,  g_x1);
    cudaGetSymbolAddress((void**)&h,   g_h);

    const int attn_smem = (4 * 64 * ATP) * (int)sizeof(float) + 64 * (int)sizeof(int);
    cudaFuncSetAttribute(attn_kernel,
                         cudaFuncAttributeMaxDynamicSharedMemorySize, attn_smem);

    // QKV projections (tf32 tensor cores)
    gemm_tf32_kernel<0><<<dim3(D_MODEL / 128, MROWS / 128), 256>>>(
        x, wq, bq, nullptr, q, MROWS, D_MODEL, D_MODEL);
    gemm_tf32_kernel<0><<<dim3(D_MODEL / 128, MROWS / 128), 256>>>(
        x, wk, bk, nullptr, k, MROWS, D_MODEL, D_MODEL);
    gemm_tf32_kernel<0><<<dim3(D_MODEL / 128, MROWS / 128), 256>>>(
        x, wv, bv, nullptr, v, MROWS, D_MODEL, D_MODEL);

    // attention
    attn_kernel<<<dim3(SEQ / 64, BATCH * NHEAD), 256, attn_smem>>>(
        q, k, v, mask, ctx);

    // output projection + residual, then LN1
    gemm_tf32_kernel<1><<<dim3(D_MODEL / 128, MROWS / 128), 256>>>(
        ctx, wo, bo, x, t, MROWS, D_MODEL, D_MODEL);
    ln_kernel<<<MROWS, 256>>>(t, ln1_g, ln1_b, 1e-5f, x1);

    // FFN
    gemm_tf32_kernel<2><<<dim3(FFDIM / 128, MROWS / 128), 256>>>(
        x1, w1, b1, nullptr, h, MROWS, FFDIM, D_MODEL);
    gemm_tf32_kernel<1><<<dim3(D_MODEL / 128, MROWS / 128), 256>>>(
        h, w2, b2, x1, t, MROWS, D_MODEL, FFDIM);

    // fused double LayerNorm epilogue
    ln2_fuse_kernel<<<MROWS, 256>>>(t, x1, lnf_g, lnf_b, ln2_g, ln2_b, out);
}

// round 3
// speedup vs baseline: 3.0361x; 1.6919x over previous
#include <cuda_runtime.h>
#include <math.h>
#include <stdint.h>

// ---------------------------------------------------------------------------
// Problem constants (fixed shapes)
// ---------------------------------------------------------------------------
#define D_MODEL 1024
#define NHEAD   16
#define HDIM    64
#define FFDIM   4096
#define BATCH   2
#define SEQ     2048
#define MROWS   (BATCH * SEQ)   // 4096

// ---------------------------------------------------------------------------
// Scratch (device globals; no allocation allowed)
// ---------------------------------------------------------------------------
__device__ float g_q  [MROWS * D_MODEL];
__device__ float g_k  [MROWS * D_MODEL];
__device__ float g_v  [MROWS * D_MODEL];
__device__ float g_ctx[MROWS * D_MODEL];
__device__ float g_t  [MROWS * D_MODEL];
__device__ float g_x1 [MROWS * D_MODEL];
__device__ float g_h  [MROWS * FFDIM];

// ---------------------------------------------------------------------------
// tf32 helpers
// ---------------------------------------------------------------------------
__device__ __forceinline__ uint32_t f2tf32(float x) {
    uint32_t r;
    asm("cvt.rna.tf32.f32 %0, %1;" : "=r"(r) : "f"(x));
    return r;
}

__device__ __forceinline__ void mma_tf32(float* c, const uint32_t* a, const uint32_t* b) {
    asm volatile(
        "mma.sync.aligned.m16n8k8.row.col.f32.tf32.tf32.f32 "
        "{%0,%1,%2,%3}, {%4,%5,%6,%7}, {%8,%9}, {%0,%1,%2,%3};"
        : "+f"(c[0]), "+f"(c[1]), "+f"(c[2]), "+f"(c[3])
        : "r"(a[0]), "r"(a[1]), "r"(a[2]), "r"(a[3]), "r"(b[0]), "r"(b[1]));
}

// ---------------------------------------------------------------------------
// tf32 tensor-core GEMM (unchanged from R2, validated)
// ---------------------------------------------------------------------------
#define SA 137
#define SB 136

template <int EPI>
__global__ void __launch_bounds__(256, 2)
gemm_tf32_kernel(const float* __restrict__ A, const float* __restrict__ W,
                 const float* __restrict__ bias, const float* __restrict__ res,
                 float* __restrict__ C, int M, int N, int K)
{
    __shared__ uint32_t As[32 * SA];
    __shared__ uint32_t Bs[32 * SB];

    const int tid     = threadIdx.x;
    const int lane    = tid & 31;
    const int warp_id = tid >> 5;
    const int g       = lane >> 2;
    const int tig     = lane & 3;
    const int wm      = (warp_id >> 2) * 64;
    const int wn      = (warp_id & 3) * 32;
    const int bm      = blockIdx.y * 128;
    const int bn      = blockIdx.x * 128;

    float acc[4][4][4];
#pragma unroll
    for (int i = 0; i < 4; i++)
#pragma unroll
        for (int j = 0; j < 4; j++)
#pragma unroll
            for (int r = 0; r < 4; r++) acc[i][j][r] = 0.0f;

    for (int k0 = 0; k0 < K; k0 += 32) {
#pragma unroll
        for (int it = 0; it < 4; it++) {
            int c  = tid + it * 256;
            int m  = c >> 3;
            int kc = (c & 7) * 4;
            float4 av = *(const float4*)(A + (size_t)(bm + m) * K + k0 + kc);
            As[(kc + 0) * SA + m] = f2tf32(av.x);
            As[(kc + 1) * SA + m] = f2tf32(av.y);
            As[(kc + 2) * SA + m] = f2tf32(av.z);
            As[(kc + 3) * SA + m] = f2tf32(av.w);
        }
#pragma unroll
        for (int it = 0; it < 4; it++) {
            int c  = tid + it * 256;
            int kr = c >> 5;
            int nc = (c & 31) * 4;
            float4 bv = *(const float4*)(W + (size_t)(k0 + kr) * N + bn + nc);
            uint4 tv;
            tv.x = f2tf32(bv.x);
            tv.y = f2tf32(bv.y);
            tv.z = f2tf32(bv.z);
            tv.w = f2tf32(bv.w);
            *(uint4*)(&Bs[kr * SB + nc]) = tv;
        }
        __syncthreads();

#pragma unroll
        for (int ks = 0; ks < 4; ks++) {
            const int kb = ks * 8;
            uint32_t af[4][4];
#pragma unroll
            for (int mt = 0; mt < 4; mt++) {
                const int mb = wm + mt * 16 + g;
                af[mt][0] = As[(kb + tig    ) * SA + mb    ];
                af[mt][1] = As[(kb + tig    ) * SA + mb + 8];
                af[mt][2] = As[(kb + tig + 4) * SA + mb    ];
                af[mt][3] = As[(kb + tig + 4) * SA + mb + 8];
            }
            uint32_t bf[4][2];
#pragma unroll
            for (int nt = 0; nt < 4; nt++) {
                const int nb = wn + nt * 8 + g;
                bf[nt][0] = Bs[(kb + tig    ) * SB + nb];
                bf[nt][1] = Bs[(kb + tig + 4) * SB + nb];
            }
#pragma unroll
            for (int mt = 0; mt < 4; mt++)
#pragma unroll
                for (int nt = 0; nt < 4; nt++)
                    mma_tf32(acc[mt][nt], af[mt], bf[nt]);
        }
        __syncthreads();
    }

#pragma unroll
    for (int mt = 0; mt < 4; mt++) {
        const int r0 = bm + wm + mt * 16 + g;
        const int r1 = r0 + 8;
#pragma unroll
        for (int nt = 0; nt < 4; nt++) {
            const int col = bn + wn + nt * 8 + tig * 2;
            float2 bv = *(const float2*)(bias + col);
            float2 v0, v1;
            v0.x = acc[mt][nt][0] + bv.x;
            v0.y = acc[mt][nt][1] + bv.y;
            v1.x = acc[mt][nt][2] + bv.x;
            v1.y = acc[mt][nt][3] + bv.y;
            if (EPI == 1) {
                float2 ra = *(const float2*)(res + (size_t)r0 * N + col);
                float2 rb = *(const float2*)(res + (size_t)r1 * N + col);
                v0.x += ra.x; v0.y += ra.y;
                v1.x += rb.x; v1.y += rb.y;
            }
            if (EPI == 2) {
                v0.x = 0.5f * v0.x * (1.0f + erff(v0.x * 0.70710678118654752f));
                v0.y = 0.5f * v0.y * (1.0f + erff(v0.y * 0.70710678118654752f));
                v1.x = 0.5f * v1.x * (1.0f + erff(v1.x * 0.70710678118654752f));
                v1.y = 0.5f * v1.y * (1.0f + erff(v1.y * 0.70710678118654752f));
            }
            *(float2*)(C + (size_t)r0 * N + col) = v0;
            *(float2*)(C + (size_t)r1 * N + col) = v1;
        }
    }
}

// ---------------------------------------------------------------------------
// Tensor-core flash attention (tf32 mma), BQ=64, BK=64, HD=64.
// 128 threads = 4 warps; each warp owns 16 q rows.
// Q/K/V/P all stored row-major in smem with stride 68 (conflict-free frags).
// ---------------------------------------------------------------------------
#define AS 68   // smem row stride (= 4 mod 32 -> conflict-free mma frag LDS)

__global__ void __launch_bounds__(128)
attn_mma_kernel(const float* __restrict__ q, const float* __restrict__ k,
                const float* __restrict__ v, const int* __restrict__ mask,
                float* __restrict__ ctx)
{
    extern __shared__ uint32_t sm[];
    uint32_t* Qs = sm;                   // [64][AS]
    uint32_t* Ks = Qs + 64 * AS;         // [64][AS]
    uint32_t* Vs = Ks + 64 * AS;         // [64][AS]
    uint32_t* Ps = Vs + 64 * AS;         // 4 warps x [16][AS]
    int*      Ms = (int*)(Ps + 4 * 16 * AS);

    const int tid  = threadIdx.x;
    const int lane = tid & 31;
    const int wid  = tid >> 5;
    const int g    = lane >> 2;
    const int tig  = lane & 3;
    const int b    = blockIdx.y >> 4;
    const int h    = blockIdx.y & 15;
    const int m0   = b * SEQ + blockIdx.x * 64;
    const size_t colh = (size_t)h * HDIM;
    uint32_t* Pw  = Ps + wid * 16 * AS;
    const int wq0 = wid * 16;

    // load Q tile, pre-scaled by 1/sqrt(HD), tf32
    for (int i = tid; i < 64 * 16; i += 128) {
        int r = i >> 4, c4 = (i & 15) * 4;
        float4 val = *(const float4*)(q + (size_t)(m0 + r) * D_MODEL + colh + c4);
        uint4 tv;
        tv.x = f2tf32(val.x * 0.125f);
        tv.y = f2tf32(val.y * 0.125f);
        tv.z = f2tf32(val.z * 0.125f);
        tv.w = f2tf32(val.w * 0.125f);
        *(uint4*)(Qs + r * AS + c4) = tv;
    }

    float m_i[2] = {-3.0e38f, -3.0e38f};
    float l_i[2] = {0.0f, 0.0f};
    float of[8][4];
#pragma unroll
    for (int nt = 0; nt < 8; nt++)
#pragma unroll
        for (int r = 0; r < 4; r++) of[nt][r] = 0.0f;

    for (int kt = 0; kt < SEQ / 64; kt++) {
        const int n0 = b * SEQ + kt * 64;
        __syncthreads();   // protect Ks/Vs (prev PV done) and Qs (first iter)
        for (int i = tid; i < 64 * 16; i += 128) {
            int r = i >> 4, c4 = (i & 15) * 4;
            float4 kv4 = *(const float4*)(k + (size_t)(n0 + r) * D_MODEL + colh + c4);
            uint4 tk;
            tk.x = f2tf32(kv4.x); tk.y = f2tf32(kv4.y);
            tk.z = f2tf32(kv4.z); tk.w = f2tf32(kv4.w);
            *(uint4*)(Ks + r * AS + c4) = tk;
            float4 vv4 = *(const float4*)(v + (size_t)(n0 + r) * D_MODEL + colh + c4);
            uint4 tv;
            tv.x = f2tf32(vv4.x); tv.y = f2tf32(vv4.y);
            tv.z = f2tf32(vv4.z); tv.w = f2tf32(vv4.w);
            *(uint4*)(Vs + r * AS + c4) = tv;
        }
        if (tid < 64) Ms[tid] = mask[b * SEQ + kt * 64 + tid];
        __syncthreads();

        // ---- scores: S = Q @ K^T  (A=Qs[q][d], B=Ks[key][d] as col-major) ----
        float sc[8][4];
#pragma unroll
        for (int nt = 0; nt < 8; nt++)
#pragma unroll
            for (int r = 0; r < 4; r++) sc[nt][r] = 0.0f;

#pragma unroll
        for (int ks = 0; ks < 8; ks++) {
            uint32_t af[4];
            const uint32_t* qr0 = Qs + (wq0 + g) * AS + ks * 8;
            af[0] = qr0[tig];
            af[2] = qr0[tig + 4];
            const uint32_t* qr1 = qr0 + 8 * AS;
            af[1] = qr1[tig];
            af[3] = qr1[tig + 4];
#pragma unroll
            for (int nt = 0; nt < 8; nt++) {
                uint32_t bf[2];
                const uint32_t* kr = Ks + (nt * 8 + g) * AS + ks * 8;
                bf[0] = kr[tig];
                bf[1] = kr[tig + 4];
                mma_tf32(sc[nt], af, bf);
            }
        }

        // ---- mask ----
#pragma unroll
        for (int nt = 0; nt < 8; nt++) {
            int c0 = nt * 8 + 2 * tig;
            if (Ms[c0] == 0)     { sc[nt][0] = -1e9f; sc[nt][2] = -1e9f; }
            if (Ms[c0 + 1] == 0) { sc[nt][1] = -1e9f; sc[nt][3] = -1e9f; }
        }

        // ---- online softmax on C fragments (2 rows per thread) ----
#pragma unroll
        for (int hh = 0; hh < 2; hh++) {
            const int i0  = hh * 2;
            const int row = hh ? (g + 8) : g;
            float tm = -3.0e38f;
#pragma unroll
            for (int nt = 0; nt < 8; nt++)
                tm = fmaxf(tm, fmaxf(sc[nt][i0], sc[nt][i0 + 1]));
            tm = fmaxf(tm, __shfl_xor_sync(0xffffffffu, tm, 1));
            tm = fmaxf(tm, __shfl_xor_sync(0xffffffffu, tm, 2));
            float nm   = fmaxf(m_i[hh], tm);
            float corr = __expf(m_i[hh] - nm);
            m_i[hh] = nm;
            float rs = 0.0f;
#pragma unroll
            for (int nt = 0; nt < 8; nt++) {
                float p0 = __expf(sc[nt][i0]     - nm);
                float p1 = __expf(sc[nt][i0 + 1] - nm);
                rs += p0 + p1;
                Pw[row * AS + nt * 8 + 2 * tig    ] = f2tf32(p0);
                Pw[row * AS + nt * 8 + 2 * tig + 1] = f2tf32(p1);
            }
            rs += __shfl_xor_sync(0xffffffffu, rs, 1);
            rs += __shfl_xor_sync(0xffffffffu, rs, 2);
            l_i[hh] = l_i[hh] * corr + rs;
#pragma unroll
            for (int nt = 0; nt < 8; nt++) {
                of[nt][i0]     *= corr;
                of[nt][i0 + 1] *= corr;
            }
        }
        __syncwarp();   // Pw visibility within the warp

        // ---- O += P @ V  (A=Pw[q][key], B=Vs[key][d] as col-major) ----
#pragma unroll
        for (int ks = 0; ks < 8; ks++) {
            uint32_t af[4];
            const uint32_t* pr0 = Pw + g * AS + ks * 8;
            af[0] = pr0[tig];
            af[2] = pr0[tig + 4];
            const uint32_t* pr1 = pr0 + 8 * AS;
            af[1] = pr1[tig];
            af[3] = pr1[tig + 4];
#pragma unroll
            for (int nt = 0; nt < 8; nt++) {
                uint32_t bf[2];
                bf[0] = Vs[(ks * 8 + tig    ) * AS + nt * 8 + g];
                bf[1] = Vs[(ks * 8 + tig + 4) * AS + nt * 8 + g];
                mma_tf32(of[nt], af, bf);
            }
        }
    }

    // ---- epilogue: normalize and write ctx ----
    const float inv0 = 1.0f / l_i[0];
    const float inv1 = 1.0f / l_i[1];
    const int r0 = m0 + wq0 + g;
    const int r1 = r0 + 8;
#pragma unroll
    for (int nt = 0; nt < 8; nt++) {
        const size_t col = colh + nt * 8 + 2 * tig;
        float2 v0 = { of[nt][0] * inv0, of[nt][1] * inv0 };
        float2 v1 = { of[nt][2] * inv1, of[nt][3] * inv1 };
        *(float2*)(ctx + (size_t)r0 * D_MODEL + col) = v0;
        *(float2*)(ctx + (size_t)r1 * D_MODEL + col) = v1;
    }
}

// ---------------------------------------------------------------------------
// LayerNorm helpers (unchanged)
// ---------------------------------------------------------------------------
__device__ __forceinline__ float block_reduce_sum(float val, float* red)
{
#pragma unroll
    for (int o = 16; o > 0; o >>= 1)
        val += __shfl_xor_sync(0xffffffffu, val, o);
    int warp = threadIdx.x >> 5;
    if ((threadIdx.x & 31) == 0) red[warp] = val;
    __syncthreads();
    if (threadIdx.x < 32) {
        float v = (threadIdx.x < 8) ? red[threadIdx.x] : 0.0f;
#pragma unroll
        for (int o = 4; o > 0; o >>= 1)
            v += __shfl_xor_sync(0xffffffffu, v, o);
        if (threadIdx.x == 0) red[0] = v;
    }
    __syncthreads();
    float r = red[0];
    __syncthreads();
    return r;
}

__global__ void __launch_bounds__(256)
ln_kernel(const float* __restrict__ in, const float* __restrict__ g,
          const float* __restrict__ bb, float eps, float* __restrict__ out)
{
    __shared__ float red[8];
    const int row = blockIdx.x;
    const float* rp = in + (size_t)row * D_MODEL;
    float vloc[4];
    float s = 0.0f;
#pragma unroll
    for (int i = 0; i < 4; i++) {
        vloc[i] = rp[threadIdx.x + i * 256];
        s += vloc[i];
    }
    float mean = block_reduce_sum(s, red) * (1.0f / D_MODEL);
    float vs = 0.0f;
#pragma unroll
    for (int i = 0; i < 4; i++) {
        float dv = vloc[i] - mean;
        vs += dv * dv;
    }
    float var  = block_reduce_sum(vs, red) * (1.0f / D_MODEL);
    float rstd = rsqrtf(var + eps);
#pragma unroll
    for (int i = 0; i < 4; i++) {
        int c = threadIdx.x + i * 256;
        out[(size_t)row * D_MODEL + c] = (vloc[i] - mean) * rstd * g[c] + bb[c];
    }
}

__global__ void __launch_bounds__(256)
ln2_fuse_kernel(const float* __restrict__ t2, const float* __restrict__ x1,
                const float* __restrict__ lnf_g, const float* __restrict__ lnf_b,
                const float* __restrict__ ln2_g, const float* __restrict__ ln2_b,
                float* __restrict__ out)
{
    __shared__ float red[8];
    const int row = blockIdx.x;
    const float* tp = t2 + (size_t)row * D_MODEL;
    const float* xp = x1 + (size_t)row * D_MODEL;
    float tv[4], xv[4];
    float s = 0.0f;
#pragma unroll
    for (int i = 0; i < 4; i++) {
        int c = threadIdx.x + i * 256;
        tv[i] = tp[c];
        xv[i] = xp[c];
        s += tv[i];
    }
    float mean1 = block_reduce_sum(s, red) * (1.0f / D_MODEL);
    float vs = 0.0f;
#pragma unroll
    for (int i = 0; i < 4; i++) {
        float dv = tv[i] - mean1;
        vs += dv * dv;
    }
    float var1  = block_reduce_sum(vs, red) * (1.0f / D_MODEL);
    float rstd1 = rsqrtf(var1 + 1e-12f);

    float u[4];
    float s2 = 0.0f;
#pragma unroll
    for (int i = 0; i < 4; i++) {
        int c = threadIdx.x + i * 256;
        float ff = (tv[i] - mean1) * rstd1 * lnf_g[c] + lnf_b[c];
        u[i] = xv[i] + ff;
        s2 += u[i];
    }
    float mean2 = block_reduce_sum(s2, red) * (1.0f / D_MODEL);
    float vs2 = 0.0f;
#pragma unroll
    for (int i = 0; i < 4; i++) {
        float dv = u[i] - mean2;
        vs2 += dv * dv;
    }
    float var2  = block_reduce_sum(vs2, red) * (1.0f / D_MODEL);
    float rstd2 = rsqrtf(var2 + 1e-5f);
#pragma unroll
    for (int i = 0; i < 4; i++) {
        int c = threadIdx.x + i * 256;
        out[(size_t)row * D_MODEL + c] = (u[i] - mean2) * rstd2 * ln2_g[c] + ln2_b[c];
    }
}

// ---------------------------------------------------------------------------
// Launcher
// ---------------------------------------------------------------------------
extern "C" void kernel_launch(void* const* d_in, const int* in_sizes, int n_in,
                              void* d_out, int out_size)
{
    const float* x      = (const float*)d_in[0];
    const int*   mask   = (const int*)  d_in[1];
    const float* wq     = (const float*)d_in[2];
    const float* bq     = (const float*)d_in[3];
    const float* wk     = (const float*)d_in[4];
    const float* bk     = (const float*)d_in[5];
    const float* wv     = (const float*)d_in[6];
    const float* bv     = (const float*)d_in[7];
    const float* wo     = (const float*)d_in[8];
    const float* bo     = (const float*)d_in[9];
    const float* ln1_g  = (const float*)d_in[10];
    const float* ln1_b  = (const float*)d_in[11];
    const float* w1     = (const float*)d_in[12];
    const float* b1     = (const float*)d_in[13];
    const float* w2     = (const float*)d_in[14];
    const float* b2     = (const float*)d_in[15];
    const float* lnf_g  = (const float*)d_in[16];
    const float* lnf_b  = (const float*)d_in[17];
    const float* ln2_g  = (const float*)d_in[18];
    const float* ln2_b  = (const float*)d_in[19];
    float* out = (float*)d_out;

    float *q, *k, *v, *ctx, *t, *x1, *h;
    cudaGetSymbolAddress((void**)&q,   g_q);
    cudaGetSymbolAddress((void**)&k,   g_k);
    cudaGetSymbolAddress((void**)&v,   g_v);
    cudaGetSymbolAddress((void**)&ctx, g_ctx);
    cudaGetSymbolAddress((void**)&t,   g_t);
    cudaGetSymbolAddress((void**)&x1,  g_x1);
    cudaGetSymbolAddress((void**)&h,   g_h);

    const int attn_smem = (64 * AS * 3 + 4 * 16 * AS) * (int)sizeof(uint32_t)
                        + 64 * (int)sizeof(int);
    cudaFuncSetAttribute(attn_mma_kernel,
                         cudaFuncAttributeMaxDynamicSharedMemorySize, attn_smem);

    // QKV projections (tf32 tensor cores)
    gemm_tf32_kernel<0><<<dim3(D_MODEL / 128, MROWS / 128), 256>>>(
        x, wq, bq, nullptr, q, MROWS, D_MODEL, D_MODEL);
    gemm_tf32_kernel<0><<<dim3(D_MODEL / 128, MROWS / 128), 256>>>(
        x, wk, bk, nullptr, k, MROWS, D_MODEL, D_MODEL);
    gemm_tf32_kernel<0><<<dim3(D_MODEL / 128, MROWS / 128), 256>>>(
        x, wv, bv, nullptr, v, MROWS, D_MODEL, D_MODEL);

    // attention (tensor cores)
    attn_mma_kernel<<<dim3(SEQ / 64, BATCH * NHEAD), 128, attn_smem>>>(
        q, k, v, mask, ctx);

    // output projection + residual, then LN1
    gemm_tf32_kernel<1><<<dim3(D_MODEL / 128, MROWS / 128), 256>>>(
        ctx, wo, bo, x, t, MROWS, D_MODEL, D_MODEL);
    ln_kernel<<<MROWS, 256>>>(t, ln1_g, ln1_b, 1e-5f, x1);

    // FFN
    gemm_tf32_kernel<2><<<dim3(FFDIM / 128, MROWS / 128), 256>>>(
        x1, w1, b1, nullptr, h, MROWS, FFDIM, D_MODEL);
    gemm_tf32_kernel<1><<<dim3(D_MODEL / 128, MROWS / 128), 256>>>(
        h, w2, b2, x1, t, MROWS, D_MODEL, FFDIM);

    // fused double LayerNorm epilogue
    ln2_fuse_kernel<<<MROWS, 256>>>(t, x1, lnf_g, lnf_b, ln2_g, ln2_b, out);
}

// round 4
// speedup vs baseline: 3.6434x; 1.2001x over previous
#include <cuda_runtime.h>
#include <math.h>
#include <stdint.h>

// ---------------------------------------------------------------------------
// Problem constants (fixed shapes)
// ---------------------------------------------------------------------------
#define D_MODEL 1024
#define NHEAD   16
#define HDIM    64
#define FFDIM   4096
#define BATCH   2
#define SEQ     2048
#define MROWS   (BATCH * SEQ)   // 4096

// ---------------------------------------------------------------------------
// Scratch (device globals; no allocation allowed)
// ---------------------------------------------------------------------------
__device__ float g_q  [MROWS * D_MODEL];
__device__ float g_k  [MROWS * D_MODEL];
__device__ float g_v  [MROWS * D_MODEL];
__device__ float g_ctx[MROWS * D_MODEL];
__device__ float g_t  [MROWS * D_MODEL];
__device__ float g_x1 [MROWS * D_MODEL];
__device__ float g_h  [MROWS * FFDIM];

// ---------------------------------------------------------------------------
// helpers
// ---------------------------------------------------------------------------
__device__ __forceinline__ void mma_tf32(float* c, const uint32_t* a, const uint32_t* b) {
    asm volatile(
        "mma.sync.aligned.m16n8k8.row.col.f32.tf32.tf32.f32 "
        "{%0,%1,%2,%3}, {%4,%5,%6,%7}, {%8,%9}, {%0,%1,%2,%3};"
        : "+f"(c[0]), "+f"(c[1]), "+f"(c[2]), "+f"(c[3])
        : "r"(a[0]), "r"(a[1]), "r"(a[2]), "r"(a[3]), "r"(b[0]), "r"(b[1]));
}

__device__ __forceinline__ void cp16(void* dst, const void* src) {
    uint32_t d = (uint32_t)__cvta_generic_to_shared(dst);
    asm volatile("cp.async.cg.shared.global [%0], [%1], 16;" :: "r"(d), "l"(src));
}
__device__ __forceinline__ void cp_commit() {
    asm volatile("cp.async.commit_group;");
}
template <int N> __device__ __forceinline__ void cp_wait() {
    asm volatile("cp.async.wait_group %0;" :: "n"(N));
}

// ---------------------------------------------------------------------------
// tf32 tensor-core GEMM, 2-stage cp.async pipeline.
// C[M,N] = A[M,K] @ W[K,N] + bias (+ epilogue)
// CTA tile 128x128x32, 256 threads (8 warps of 64x32).
// A smem: [m][k] row-major, stride 36 (4 mod 32 -> conflict-free frag LDS).
// B smem: [k][n] row-major, stride 136.
// Raw fp32 bits fed to tf32 mma (mantissa truncation).
// ---------------------------------------------------------------------------
#define AST 36
#define BST 136
#define GEMM_SMEM ((2 * 128 * AST + 2 * 32 * BST) * 4)

template <int EPI>
__global__ void __launch_bounds__(256)
gemm_tf32_kernel(const float* __restrict__ A, const float* __restrict__ W,
                 const float* __restrict__ bias, const float* __restrict__ res,
                 float* __restrict__ C, int M, int N, int K)
{
    extern __shared__ uint32_t smg[];
    uint32_t* As = smg;                     // 2 x [128][AST]
    uint32_t* Bs = smg + 2 * 128 * AST;     // 2 x [32][BST]

    const int tid     = threadIdx.x;
    const int lane    = tid & 31;
    const int warp_id = tid >> 5;
    const int g       = lane >> 2;
    const int tig     = lane & 3;
    const int wm      = (warp_id >> 2) * 64;
    const int wn      = (warp_id & 3) * 32;
    const int bm      = blockIdx.y * 128;
    const int bn      = blockIdx.x * 128;

    // per-thread load coordinates (4 chunks each for A and B per stage)
    int am[4], ac[4], bk[4], bnc[4];
#pragma unroll
    for (int it = 0; it < 4; it++) {
        int c = tid + it * 256;
        am[it]  = c >> 3;            // 0..127
        ac[it]  = (c & 7) * 4;       // 0..28
        bk[it]  = c >> 5;            // 0..31
        bnc[it] = (c & 31) * 4;      // 0..124
    }

    float acc[4][4][4];
#pragma unroll
    for (int i = 0; i < 4; i++)
#pragma unroll
        for (int j = 0; j < 4; j++)
#pragma unroll
            for (int r = 0; r < 4; r++) acc[i][j][r] = 0.0f;

    const int KT = K >> 5;

    // ---- prefetch stage 0 ----
#pragma unroll
    for (int it = 0; it < 4; it++) {
        cp16(As + am[it] * AST + ac[it],
             A + (size_t)(bm + am[it]) * K + ac[it]);
        cp16(Bs + bk[it] * BST + bnc[it],
             W + (size_t)bk[it] * N + bn + bnc[it]);
    }
    cp_commit();

    for (int kt = 0; kt < KT; kt++) {
        const int cur = kt & 1;
        if (kt + 1 < KT) {
            const int nxt = cur ^ 1;
            const int k0  = (kt + 1) << 5;
#pragma unroll
            for (int it = 0; it < 4; it++) {
                cp16(As + nxt * 128 * AST + am[it] * AST + ac[it],
                     A + (size_t)(bm + am[it]) * K + k0 + ac[it]);
                cp16(Bs + nxt * 32 * BST + bk[it] * BST + bnc[it],
                     W + (size_t)(k0 + bk[it]) * N + bn + bnc[it]);
            }
            cp_commit();
            cp_wait<1>();
        } else {
            cp_wait<0>();
        }
        __syncthreads();

        const uint32_t* Ac = As + cur * 128 * AST;
        const uint32_t* Bc = Bs + cur * 32 * BST;
#pragma unroll
        for (int ks = 0; ks < 4; ks++) {
            const int kb = ks * 8;
            uint32_t af[4][4];
#pragma unroll
            for (int mt = 0; mt < 4; mt++) {
                const uint32_t* ar0 = Ac + (wm + mt * 16 + g) * AST + kb;
                const uint32_t* ar1 = ar0 + 8 * AST;
                af[mt][0] = ar0[tig];
                af[mt][1] = ar1[tig];
                af[mt][2] = ar0[tig + 4];
                af[mt][3] = ar1[tig + 4];
            }
            uint32_t bf[4][2];
#pragma unroll
            for (int nt = 0; nt < 4; nt++) {
                const int nb = wn + nt * 8 + g;
                bf[nt][0] = Bc[(kb + tig    ) * BST + nb];
                bf[nt][1] = Bc[(kb + tig + 4) * BST + nb];
            }
#pragma unroll
            for (int mt = 0; mt < 4; mt++)
#pragma unroll
                for (int nt = 0; nt < 4; nt++)
                    mma_tf32(acc[mt][nt], af[mt], bf[nt]);
        }
        __syncthreads();
    }

    // ---- epilogue ----
#pragma unroll
    for (int mt = 0; mt < 4; mt++) {
        const int r0 = bm + wm + mt * 16 + g;
        const int r1 = r0 + 8;
#pragma unroll
        for (int nt = 0; nt < 4; nt++) {
            const int col = bn + wn + nt * 8 + tig * 2;
            float2 bv = *(const float2*)(bias + col);
            float2 v0, v1;
            v0.x = acc[mt][nt][0] + bv.x;
            v0.y = acc[mt][nt][1] + bv.y;
            v1.x = acc[mt][nt][2] + bv.x;
            v1.y = acc[mt][nt][3] + bv.y;
            if (EPI == 1) {
                float2 ra = *(const float2*)(res + (size_t)r0 * N + col);
                float2 rb = *(const float2*)(res + (size_t)r1 * N + col);
                v0.x += ra.x; v0.y += ra.y;
                v1.x += rb.x; v1.y += rb.y;
            }
            if (EPI == 2) {
                v0.x = 0.5f * v0.x * (1.0f + erff(v0.x * 0.70710678118654752f));
                v0.y = 0.5f * v0.y * (1.0f + erff(v0.y * 0.70710678118654752f));
                v1.x = 0.5f * v1.x * (1.0f + erff(v1.x * 0.70710678118654752f));
                v1.y = 0.5f * v1.y * (1.0f + erff(v1.y * 0.70710678118654752f));
            }
            *(float2*)(C + (size_t)r0 * N + col) = v0;
            *(float2*)(C + (size_t)r1 * N + col) = v1;
        }
    }
}

// ---------------------------------------------------------------------------
// Tensor-core flash attention (tf32 mma, raw-bit operands).
// BQ=128, BK=64, HD=64. 256 threads = 8 warps; each warp owns 16 q rows.
// All tiles loaded via cp.async. Softmax scale 1/8 folded into exp args.
// ---------------------------------------------------------------------------
#define AS 68   // smem row stride (4 mod 32 -> conflict-free mma frag LDS)
#define ATTN_SMEM ((128 * AS + 64 * AS + 64 * AS + 128 * AS) * 4 + 64 * 4)

__global__ void __launch_bounds__(256)
attn_mma_kernel(const float* __restrict__ q, const float* __restrict__ k,
                const float* __restrict__ v, const int* __restrict__ mask,
                float* __restrict__ ctx)
{
    extern __shared__ uint32_t sm[];
    uint32_t* Qs = sm;                    // [128][AS]
    uint32_t* Ks = Qs + 128 * AS;         // [64][AS]
    uint32_t* Vs = Ks + 64 * AS;          // [64][AS]
    uint32_t* Ps = Vs + 64 * AS;          // 8 warps x [16][AS]
    int*      Ms = (int*)(Ps + 128 * AS);

    const int tid  = threadIdx.x;
    const int lane = tid & 31;
    const int wid  = tid >> 5;
    const int g    = lane >> 2;
    const int tig  = lane & 3;
    const int b    = blockIdx.y >> 4;
    const int h    = blockIdx.y & 15;
    const int m0   = b * SEQ + blockIdx.x * 128;
    const size_t colh = (size_t)h * HDIM;
    uint32_t* Pw  = Ps + wid * 16 * AS;
    const int wq0 = wid * 16;
    const float SC = 0.125f;   // 1/sqrt(64)

    // ---- async-load Q tile (raw fp32 bits) ----
#pragma unroll
    for (int it = 0; it < 8; it++) {
        int c = tid + it * 256;           // 0..2047
        int r = c >> 4, c4 = (c & 15) * 4;
        cp16(Qs + r * AS + c4, q + (size_t)(m0 + r) * D_MODEL + colh + c4);
    }
    cp_commit();

    float m_i[2] = {-3.0e38f, -3.0e38f};
    float l_i[2] = {0.0f, 0.0f};
    float of[8][4];
#pragma unroll
    for (int nt = 0; nt < 8; nt++)
#pragma unroll
        for (int r = 0; r < 4; r++) of[nt][r] = 0.0f;

    for (int kt = 0; kt < SEQ / 64; kt++) {
        const int n0 = b * SEQ + kt * 64;
        __syncthreads();   // previous tile's PV reads of Ks/Vs complete
#pragma unroll
        for (int it = 0; it < 4; it++) {
            int c = tid + it * 256;       // 0..1023
            int r = c >> 4, c4 = (c & 15) * 4;
            cp16(Ks + r * AS + c4, k + (size_t)(n0 + r) * D_MODEL + colh + c4);
            cp16(Vs + r * AS + c4, v + (size_t)(n0 + r) * D_MODEL + colh + c4);
        }
        cp_commit();
        if (tid < 64) Ms[tid] = mask[b * SEQ + kt * 64 + tid];
        cp_wait<0>();
        __syncthreads();

        // ---- scores: S = Q @ K^T ----
        float sc[8][4];
#pragma unroll
        for (int nt = 0; nt < 8; nt++)
#pragma unroll
            for (int r = 0; r < 4; r++) sc[nt][r] = 0.0f;

#pragma unroll
        for (int ks = 0; ks < 8; ks++) {
            uint32_t af[4];
            const uint32_t* qr0 = Qs + (wq0 + g) * AS + ks * 8;
            const uint32_t* qr1 = qr0 + 8 * AS;
            af[0] = qr0[tig];
            af[1] = qr1[tig];
            af[2] = qr0[tig + 4];
            af[3] = qr1[tig + 4];
#pragma unroll
            for (int nt = 0; nt < 8; nt++) {
                uint32_t bf[2];
                const uint32_t* kr = Ks + (nt * 8 + g) * AS + ks * 8;
                bf[0] = kr[tig];
                bf[1] = kr[tig + 4];
                mma_tf32(sc[nt], af, bf);
            }
        }

        // ---- mask ----
#pragma unroll
        for (int nt = 0; nt < 8; nt++) {
            int c0 = nt * 8 + 2 * tig;
            if (Ms[c0] == 0)     { sc[nt][0] = -1e9f; sc[nt][2] = -1e9f; }
            if (Ms[c0 + 1] == 0) { sc[nt][1] = -1e9f; sc[nt][3] = -1e9f; }
        }

        // ---- online softmax (scale folded into exp) ----
#pragma unroll
        for (int hh = 0; hh < 2; hh++) {
            const int i0  = hh * 2;
            const int row = hh ? (g + 8) : g;
            float tm = -3.0e38f;
#pragma unroll
            for (int nt = 0; nt < 8; nt++)
                tm = fmaxf(tm, fmaxf(sc[nt][i0], sc[nt][i0 + 1]));
            tm = fmaxf(tm, __shfl_xor_sync(0xffffffffu, tm, 1));
            tm = fmaxf(tm, __shfl_xor_sync(0xffffffffu, tm, 2));
            float nm   = fmaxf(m_i[hh], tm);
            float corr = __expf((m_i[hh] - nm) * SC);
            m_i[hh] = nm;
            float rs = 0.0f;
#pragma unroll
            for (int nt = 0; nt < 8; nt++) {
                float p0 = __expf((sc[nt][i0]     - nm) * SC);
                float p1 = __expf((sc[nt][i0 + 1] - nm) * SC);
                rs += p0 + p1;
                Pw[row * AS + nt * 8 + 2 * tig    ] = __float_as_uint(p0);
                Pw[row * AS + nt * 8 + 2 * tig + 1] = __float_as_uint(p1);
            }
            rs += __shfl_xor_sync(0xffffffffu, rs, 1);
            rs += __shfl_xor_sync(0xffffffffu, rs, 2);
            l_i[hh] = l_i[hh] * corr + rs;
#pragma unroll
            for (int nt = 0; nt < 8; nt++) {
                of[nt][i0]     *= corr;
                of[nt][i0 + 1] *= corr;
            }
        }
        __syncwarp();

        // ---- O += P @ V ----
#pragma unroll
        for (int ks = 0; ks < 8; ks++) {
            uint32_t af[4];
            const uint32_t* pr0 = Pw + g * AS + ks * 8;
            const uint32_t* pr1 = pr0 + 8 * AS;
            af[0] = pr0[tig];
            af[1] = pr1[tig];
            af[2] = pr0[tig + 4];
            af[3] = pr1[tig + 4];
#pragma unroll
            for (int nt = 0; nt < 8; nt++) {
                uint32_t bf[2];
                bf[0] = Vs[(ks * 8 + tig    ) * AS + nt * 8 + g];
                bf[1] = Vs[(ks * 8 + tig + 4) * AS + nt * 8 + g];
                mma_tf32(of[nt], af, bf);
            }
        }
    }

    // ---- epilogue ----
    const float inv0 = 1.0f / l_i[0];
    const float inv1 = 1.0f / l_i[1];
    const int r0 = m0 + wq0 + g;
    const int r1 = r0 + 8;
#pragma unroll
    for (int nt = 0; nt < 8; nt++) {
        const size_t col = colh + nt * 8 + 2 * tig;
        float2 v0 = { of[nt][0] * inv0, of[nt][1] * inv0 };
        float2 v1 = { of[nt][2] * inv1, of[nt][3] * inv1 };
        *(float2*)(ctx + (size_t)r0 * D_MODEL + col) = v0;
        *(float2*)(ctx + (size_t)r1 * D_MODEL + col) = v1;
    }
}

// ---------------------------------------------------------------------------
// LayerNorm kernels (unchanged)
// ---------------------------------------------------------------------------
__device__ __forceinline__ float block_reduce_sum(float val, float* red)
{
#pragma unroll
    for (int o = 16; o > 0; o >>= 1)
        val += __shfl_xor_sync(0xffffffffu, val, o);
    int warp = threadIdx.x >> 5;
    if ((threadIdx.x & 31) == 0) red[warp] = val;
    __syncthreads();
    if (threadIdx.x < 32) {
        float v = (threadIdx.x < 8) ? red[threadIdx.x] : 0.0f;
#pragma unroll
        for (int o = 4; o > 0; o >>= 1)
            v += __shfl_xor_sync(0xffffffffu, v, o);
        if (threadIdx.x == 0) red[0] = v;
    }
    __syncthreads();
    float r = red[0];
    __syncthreads();
    return r;
}

__global__ void __launch_bounds__(256)
ln_kernel(const float* __restrict__ in, const float* __restrict__ g,
          const float* __restrict__ bb, float eps, float* __restrict__ out)
{
    __shared__ float red[8];
    const int row = blockIdx.x;
    const float* rp = in + (size_t)row * D_MODEL;
    float vloc[4];
    float s = 0.0f;
#pragma unroll
    for (int i = 0; i < 4; i++) {
        vloc[i] = rp[threadIdx.x + i * 256];
        s += vloc[i];
    }
    float mean = block_reduce_sum(s, red) * (1.0f / D_MODEL);
    float vs = 0.0f;
#pragma unroll
    for (int i = 0; i < 4; i++) {
        float dv = vloc[i] - mean;
        vs += dv * dv;
    }
    float var  = block_reduce_sum(vs, red) * (1.0f / D_MODEL);
    float rstd = rsqrtf(var + eps);
#pragma unroll
    for (int i = 0; i < 4; i++) {
        int c = threadIdx.x + i * 256;
        out[(size_t)row * D_MODEL + c] = (vloc[i] - mean) * rstd * g[c] + bb[c];
    }
}

__global__ void __launch_bounds__(256)
ln2_fuse_kernel(const float* __restrict__ t2, const float* __restrict__ x1,
                const float* __restrict__ lnf_g, const float* __restrict__ lnf_b,
                const float* __restrict__ ln2_g, const float* __restrict__ ln2_b,
                float* __restrict__ out)
{
    __shared__ float red[8];
    const int row = blockIdx.x;
    const float* tp = t2 + (size_t)row * D_MODEL;
    const float* xp = x1 + (size_t)row * D_MODEL;
    float tv[4], xv[4];
    float s = 0.0f;
#pragma unroll
    for (int i = 0; i < 4; i++) {
        int c = threadIdx.x + i * 256;
        tv[i] = tp[c];
        xv[i] = xp[c];
        s += tv[i];
    }
    float mean1 = block_reduce_sum(s, red) * (1.0f / D_MODEL);
    float vs = 0.0f;
#pragma unroll
    for (int i = 0; i < 4; i++) {
        float dv = tv[i] - mean1;
        vs += dv * dv;
    }
    float var1  = block_reduce_sum(vs, red) * (1.0f / D_MODEL);
    float rstd1 = rsqrtf(var1 + 1e-12f);

    float u[4];
    float s2 = 0.0f;
#pragma unroll
    for (int i = 0; i < 4; i++) {
        int c = threadIdx.x + i * 256;
        float ff = (tv[i] - mean1) * rstd1 * lnf_g[c] + lnf_b[c];
        u[i] = xv[i] + ff;
        s2 += u[i];
    }
    float mean2 = block_reduce_sum(s2, red) * (1.0f / D_MODEL);
    float vs2 = 0.0f;
#pragma unroll
    for (int i = 0; i < 4; i++) {
        float dv = u[i] - mean2;
        vs2 += dv * dv;
    }
    float var2  = block_reduce_sum(vs2, red) * (1.0f / D_MODEL);
    float rstd2 = rsqrtf(var2 + 1e-5f);
#pragma unroll
    for (int i = 0; i < 4; i++) {
        int c = threadIdx.x + i * 256;
        out[(size_t)row * D_MODEL + c] = (u[i] - mean2) * rstd2 * ln2_g[c] + ln2_b[c];
    }
}

// ---------------------------------------------------------------------------
// Launcher
// ---------------------------------------------------------------------------
extern "C" void kernel_launch(void* const* d_in, const int* in_sizes, int n_in,
                              void* d_out, int out_size)
{
    const float* x      = (const float*)d_in[0];
    const int*   mask   = (const int*)  d_in[1];
    const float* wq     = (const float*)d_in[2];
    const float* bq     = (const float*)d_in[3];
    const float* wk     = (const float*)d_in[4];
    const float* bk     = (const float*)d_in[5];
    const float* wv     = (const float*)d_in[6];
    const float* bv     = (const float*)d_in[7];
    const float* wo     = (const float*)d_in[8];
    const float* bo     = (const float*)d_in[9];
    const float* ln1_g  = (const float*)d_in[10];
    const float* ln1_b  = (const float*)d_in[11];
    const float* w1     = (const float*)d_in[12];
    const float* b1     = (const float*)d_in[13];
    const float* w2     = (const float*)d_in[14];
    const float* b2     = (const float*)d_in[15];
    const float* lnf_g  = (const float*)d_in[16];
    const float* lnf_b  = (const float*)d_in[17];
    const float* ln2_g  = (const float*)d_in[18];
    const float* ln2_b  = (const float*)d_in[19];
    float* out = (float*)d_out;

    float *q, *k, *v, *ctx, *t, *x1, *h;
    cudaGetSymbolAddress((void**)&q,   g_q);
    cudaGetSymbolAddress((void**)&k,   g_k);
    cudaGetSymbolAddress((void**)&v,   g_v);
    cudaGetSymbolAddress((void**)&ctx, g_ctx);
    cudaGetSymbolAddress((void**)&t,   g_t);
    cudaGetSymbolAddress((void**)&x1,  g_x1);
    cudaGetSymbolAddress((void**)&h,   g_h);

    cudaFuncSetAttribute(gemm_tf32_kernel<0>,
                         cudaFuncAttributeMaxDynamicSharedMemorySize, GEMM_SMEM);
    cudaFuncSetAttribute(gemm_tf32_kernel<1>,
                         cudaFuncAttributeMaxDynamicSharedMemorySize, GEMM_SMEM);
    cudaFuncSetAttribute(gemm_tf32_kernel<2>,
                         cudaFuncAttributeMaxDynamicSharedMemorySize, GEMM_SMEM);
    cudaFuncSetAttribute(attn_mma_kernel,
                         cudaFuncAttributeMaxDynamicSharedMemorySize, ATTN_SMEM);

    // QKV projections
    gemm_tf32_kernel<0><<<dim3(D_MODEL / 128, MROWS / 128), 256, GEMM_SMEM>>>(
        x, wq, bq, nullptr, q, MROWS, D_MODEL, D_MODEL);
    gemm_tf32_kernel<0><<<dim3(D_MODEL / 128, MROWS / 128), 256, GEMM_SMEM>>>(
        x, wk, bk, nullptr, k, MROWS, D_MODEL, D_MODEL);
    gemm_tf32_kernel<0><<<dim3(D_MODEL / 128, MROWS / 128), 256, GEMM_SMEM>>>(
        x, wv, bv, nullptr, v, MROWS, D_MODEL, D_MODEL);

    // attention
    attn_mma_kernel<<<dim3(SEQ / 128, BATCH * NHEAD), 256, ATTN_SMEM>>>(
        q, k, v, mask, ctx);

    // output projection + residual, then LN1
    gemm_tf32_kernel<1><<<dim3(D_MODEL / 128, MROWS / 128), 256, GEMM_SMEM>>>(
        ctx, wo, bo, x, t, MROWS, D_MODEL, D_MODEL);
    ln_kernel<<<MROWS, 256>>>(t, ln1_g, ln1_b, 1e-5f, x1);

    // FFN
    gemm_tf32_kernel<2><<<dim3(FFDIM / 128, MROWS / 128), 256, GEMM_SMEM>>>(
        x1, w1, b1, nullptr, h, MROWS, FFDIM, D_MODEL);
    gemm_tf32_kernel<1><<<dim3(D_MODEL / 128, MROWS / 128), 256, GEMM_SMEM>>>(
        h, w2, b2, x1, t, MROWS, D_MODEL, FFDIM);

    // fused double LayerNorm epilogue
    ln2_fuse_kernel<<<MROWS, 256>>>(t, x1, lnf_g, lnf_b, ln2_g, ln2_b, out);
}

// round 6
// speedup vs baseline: 3.6464x; 1.0008x over previous
#include <cuda_runtime.h>
#include <math.h>
#include <stdint.h>

// ---------------------------------------------------------------------------
// Problem constants (fixed shapes)
// ---------------------------------------------------------------------------
#define D_MODEL 1024
#define NHEAD   16
#define HDIM    64
#define FFDIM   4096
#define BATCH   2
#define SEQ     2048
#define MROWS   (BATCH * SEQ)   // 4096

// ---------------------------------------------------------------------------
// Scratch (device globals; no allocation allowed)
// ---------------------------------------------------------------------------
__device__ float g_q  [MROWS * D_MODEL];
__device__ float g_k  [MROWS * D_MODEL];
__device__ float g_v  [MROWS * D_MODEL];
__device__ float g_ctx[MROWS * D_MODEL];
__device__ float g_t  [MROWS * D_MODEL];
__device__ float g_x1 [MROWS * D_MODEL];
__device__ float g_h  [MROWS * FFDIM];

// ---------------------------------------------------------------------------
// helpers
// ---------------------------------------------------------------------------
__device__ __forceinline__ void mma_tf32(float* c, const uint32_t* a, const uint32_t* b) {
    asm volatile(
        "mma.sync.aligned.m16n8k8.row.col.f32.tf32.tf32.f32 "
        "{%0,%1,%2,%3}, {%4,%5,%6,%7}, {%8,%9}, {%0,%1,%2,%3};"
        : "+f"(c[0]), "+f"(c[1]), "+f"(c[2]), "+f"(c[3])
        : "r"(a[0]), "r"(a[1]), "r"(a[2]), "r"(a[3]), "r"(b[0]), "r"(b[1]));
}

__device__ __forceinline__ void cp16(const void* dst, const void* src) {
    uint32_t d = (uint32_t)__cvta_generic_to_shared(dst);
    asm volatile("cp.async.cg.shared.global [%0], [%1], 16;" :: "r"(d), "l"(src));
}
__device__ __forceinline__ void cp_commit() {
    asm volatile("cp.async.commit_group;");
}
template <int N> __device__ __forceinline__ void cp_wait() {
    asm volatile("cp.async.wait_group %0;" :: "n"(N));
}

__device__ __forceinline__ float fexp2(float x) {
    float r;
    asm("ex2.approx.ftz.f32 %0, %1;" : "=f"(r) : "f"(x));
    return r;
}

// ---------------------------------------------------------------------------
// tf32 tensor-core GEMM, 3-stage cp.async pipeline, 1 sync per k-tile.
// C[M,N] = A[M,K] @ W[K,N] + bias (+ epilogue)
// CTA tile 128x128x32, 256 threads (8 warps of 64x32).
// A smem: [m][k] stride 36; B smem: [k][n] stride 136. Raw fp32 bits -> tf32.
// ---------------------------------------------------------------------------
#define AST 36
#define BST 136
#define STG_A (128 * AST)
#define STG_B (32 * BST)
#define GEMM_SMEM ((3 * STG_A + 3 * STG_B) * 4)

template <int EPI>
__global__ void __launch_bounds__(256)
gemm_tf32_kernel(const float* __restrict__ A, const float* __restrict__ W,
                 const float* __restrict__ bias, const float* __restrict__ res,
                 float* __restrict__ C, int M, int N, int K)
{
    extern __shared__ uint32_t smg[];
    uint32_t* As = smg;                 // 3 x [128][AST]
    uint32_t* Bs = smg + 3 * STG_A;     // 3 x [32][BST]

    const int tid     = threadIdx.x;
    const int lane    = tid & 31;
    const int warp_id = tid >> 5;
    const int g       = lane >> 2;
    const int tig     = lane & 3;
    const int wm      = (warp_id >> 2) * 64;
    const int wn      = (warp_id & 3) * 32;
    const int bm      = blockIdx.y * 128;
    const int bn      = blockIdx.x * 128;

    int am[4], ac[4], bk[4], bnc[4];
#pragma unroll
    for (int it = 0; it < 4; it++) {
        int c = tid + it * 256;
        am[it]  = c >> 3;
        ac[it]  = (c & 7) * 4;
        bk[it]  = c >> 5;
        bnc[it] = (c & 31) * 4;
    }

    float acc[4][4][4];
#pragma unroll
    for (int i = 0; i < 4; i++)
#pragma unroll
        for (int j = 0; j < 4; j++)
#pragma unroll
            for (int r = 0; r < 4; r++) acc[i][j][r] = 0.0f;

    const int KT = K >> 5;

    // prefetch stages 0 and 1
#pragma unroll
    for (int s = 0; s < 2; s++) {
        const int k0 = s << 5;
#pragma unroll
        for (int it = 0; it < 4; it++) {
            cp16(As + s * STG_A + am[it] * AST + ac[it],
                 A + (size_t)(bm + am[it]) * K + k0 + ac[it]);
            cp16(Bs + s * STG_B + bk[it] * BST + bnc[it],
                 W + (size_t)(k0 + bk[it]) * N + bn + bnc[it]);
        }
        cp_commit();
    }

    int cur = 0;
    for (int kt = 0; kt < KT; kt++) {
        if (kt + 2 < KT) cp_wait<1>(); else cp_wait<0>();
        __syncthreads();

        // prefetch stage kt+2 (buffer held stage kt-1, released by the sync)
        if (kt + 2 < KT) {
            int nb = cur + 2;
            if (nb >= 3) nb -= 3;
            const int k0 = (kt + 2) << 5;
#pragma unroll
            for (int it = 0; it < 4; it++) {
                cp16(As + nb * STG_A + am[it] * AST + ac[it],
                     A + (size_t)(bm + am[it]) * K + k0 + ac[it]);
                cp16(Bs + nb * STG_B + bk[it] * BST + bnc[it],
                     W + (size_t)(k0 + bk[it]) * N + bn + bnc[it]);
            }
            cp_commit();
        }

        const uint32_t* Ac = As + cur * STG_A;
        const uint32_t* Bc = Bs + cur * STG_B;
#pragma unroll
        for (int ks = 0; ks < 4; ks++) {
            const int kb = ks * 8;
            uint32_t af[4][4];
#pragma unroll
            for (int mt = 0; mt < 4; mt++) {
                const uint32_t* ar0 = Ac + (wm + mt * 16 + g) * AST + kb;
                const uint32_t* ar1 = ar0 + 8 * AST;
                af[mt][0] = ar0[tig];
                af[mt][1] = ar1[tig];
                af[mt][2] = ar0[tig + 4];
                af[mt][3] = ar1[tig + 4];
            }
            uint32_t bf[4][2];
#pragma unroll
            for (int nt = 0; nt < 4; nt++) {
                const int nb2 = wn + nt * 8 + g;
                bf[nt][0] = Bc[(kb + tig    ) * BST + nb2];
                bf[nt][1] = Bc[(kb + tig + 4) * BST + nb2];
            }
#pragma unroll
            for (int mt = 0; mt < 4; mt++)
#pragma unroll
                for (int nt = 0; nt < 4; nt++)
                    mma_tf32(acc[mt][nt], af[mt], bf[nt]);
        }
        cur++;
        if (cur >= 3) cur -= 3;
    }

    // ---- epilogue ----
#pragma unroll
    for (int mt = 0; mt < 4; mt++) {
        const int r0 = bm + wm + mt * 16 + g;
        const int r1 = r0 + 8;
#pragma unroll
        for (int nt = 0; nt < 4; nt++) {
            const int col = bn + wn + nt * 8 + tig * 2;
            float2 bv = *(const float2*)(bias + col);
            float2 v0, v1;
            v0.x = acc[mt][nt][0] + bv.x;
            v0.y = acc[mt][nt][1] + bv.y;
            v1.x = acc[mt][nt][2] + bv.x;
            v1.y = acc[mt][nt][3] + bv.y;
            if (EPI == 1) {
                float2 ra = *(const float2*)(res + (size_t)r0 * N + col);
                float2 rb = *(const float2*)(res + (size_t)r1 * N + col);
                v0.x += ra.x; v0.y += ra.y;
                v1.x += rb.x; v1.y += rb.y;
            }
            if (EPI == 2) {
                v0.x = 0.5f * v0.x * (1.0f + erff(v0.x * 0.70710678118654752f));
                v0.y = 0.5f * v0.y * (1.0f + erff(v0.y * 0.70710678118654752f));
                v1.x = 0.5f * v1.x * (1.0f + erff(v1.x * 0.70710678118654752f));
                v1.y = 0.5f * v1.y * (1.0f + erff(v1.y * 0.70710678118654752f));
            }
            *(float2*)(C + (size_t)r0 * N + col) = v0;
            *(float2*)(C + (size_t)r1 * N + col) = v1;
        }
    }
}

// ---------------------------------------------------------------------------
// Tensor-core flash attention (tf32 mma, raw-bit operands), software-pipelined
// K/V loads. BQ=128, BK=64, HD=64. 256 threads = 8 warps.
// Per tile: next-K load overlaps softmax+PV; next-V load overlaps next scores.
// ---------------------------------------------------------------------------
#define AS 68
#define ATTN_SMEM ((128 * AS + 64 * AS + 64 * AS + 128 * AS) * 4 + 64 * 4)
#define NT (SEQ / 64)

__global__ void __launch_bounds__(256)
attn_mma_kernel(const float* __restrict__ q, const float* __restrict__ k,
                const float* __restrict__ v, const int* __restrict__ mask,
                float* __restrict__ ctx)
{
    extern __shared__ uint32_t sm[];
    uint32_t* Qs = sm;                    // [128][AS]
    uint32_t* Ks = Qs + 128 * AS;         // [64][AS]
    uint32_t* Vs = Ks + 64 * AS;          // [64][AS]
    uint32_t* Ps = Vs + 64 * AS;          // 8 warps x [16][AS]
    int*      Ms = (int*)(Ps + 128 * AS); // 64 (mask for current tile)

    const int tid  = threadIdx.x;
    const int lane = tid & 31;
    const int wid  = tid >> 5;
    const int g    = lane >> 2;
    const int tig  = lane & 3;
    const int b    = blockIdx.y >> 4;
    const int h    = blockIdx.y & 15;
    const int m0   = b * SEQ + blockIdx.x * 128;
    const size_t colh = (size_t)h * HDIM;
    uint32_t* Pw  = Ps + wid * 16 * AS;
    const int wq0 = wid * 16;
    const float SCL2 = 0.125f * 1.44269504088896340736f;  // (1/sqrt(64))*log2(e)

    // ---- prologue: Q+K0 as one group, V0 as a second group ----
#pragma unroll
    for (int it = 0; it < 8; it++) {
        int c = tid + it * 256;
        int r = c >> 4, c4 = (c & 15) * 4;
        cp16(Qs + r * AS + c4, q + (size_t)(m0 + r) * D_MODEL + colh + c4);
    }
#pragma unroll
    for (int it = 0; it < 4; it++) {
        int c = tid + it * 256;
        int r = c >> 4, c4 = (c & 15) * 4;
        cp16(Ks + r * AS + c4, k + (size_t)(b * SEQ + r) * D_MODEL + colh + c4);
    }
    cp_commit();   // group {Q, K0}
#pragma unroll
    for (int it = 0; it < 4; it++) {
        int c = tid + it * 256;
        int r = c >> 4, c4 = (c & 15) * 4;
        cp16(Vs + r * AS + c4, v + (size_t)(b * SEQ + r) * D_MODEL + colh + c4);
    }
    cp_commit();   // group {V0}
    if (tid < 64) Ms[tid] = mask[b * SEQ + tid];

    float m_i[2] = {-3.0e38f, -3.0e38f};
    float l_i[2] = {0.0f, 0.0f};
    float of[8][4];
#pragma unroll
    for (int nt = 0; nt < 8; nt++)
#pragma unroll
        for (int r = 0; r < 4; r++) of[nt][r] = 0.0f;

    cp_wait<1>();      // Q + K0 done locally (pending: V0)
    __syncthreads();   // Q/K0/Ms visible to all

    for (int kt = 0; kt < NT; kt++) {
        const bool more = (kt + 1 < NT);
        const int n1 = b * SEQ + (kt + 1) * 64;   // next tile base

        // ---- scores: S = Q @ K^T (reads Ks) ----
        float sc[8][4];
#pragma unroll
        for (int nt = 0; nt < 8; nt++)
#pragma unroll
            for (int r = 0; r < 4; r++) sc[nt][r] = 0.0f;

#pragma unroll
        for (int ks = 0; ks < 8; ks++) {
            uint32_t af[4];
            const uint32_t* qr0 = Qs + (wq0 + g) * AS + ks * 8;
            const uint32_t* qr1 = qr0 + 8 * AS;
            af[0] = qr0[tig];
            af[1] = qr1[tig];
            af[2] = qr0[tig + 4];
            af[3] = qr1[tig + 4];
#pragma unroll
            for (int nt = 0; nt < 8; nt++) {
                uint32_t bf[2];
                const uint32_t* kr = Ks + (nt * 8 + g) * AS + ks * 8;
                bf[0] = kr[tig];
                bf[1] = kr[tig + 4];
                mma_tf32(sc[nt], af, bf);
            }
        }

        // ---- mask (Ms for tile kt, visible since entry sync) ----
#pragma unroll
        for (int nt = 0; nt < 8; nt++) {
            int c0 = nt * 8 + 2 * tig;
            if (Ms[c0] == 0)     { sc[nt][0] = -1e9f; sc[nt][2] = -1e9f; }
            if (Ms[c0 + 1] == 0) { sc[nt][1] = -1e9f; sc[nt][3] = -1e9f; }
        }

        __syncthreads();   // S1: all warps done reading Ks and Ms

        // ---- prefetch next K into Ks (overlaps softmax + PV) ----
        if (more) {
#pragma unroll
            for (int it = 0; it < 4; it++) {
                int c = tid + it * 256;
                int r = c >> 4, c4 = (c & 15) * 4;
                cp16(Ks + r * AS + c4, k + (size_t)(n1 + r) * D_MODEL + colh + c4);
            }
            cp_commit();   // pending: {V_kt, K_next}
            if (tid < 64) Ms[tid] = mask[n1 + tid];   // next mask
        }

        // ---- online softmax (exp2, skip rescale when max unchanged) ----
#pragma unroll
        for (int hh = 0; hh < 2; hh++) {
            const int i0  = hh * 2;
            const int row = hh ? (g + 8) : g;
            float tm = -3.0e38f;
#pragma unroll
            for (int nt = 0; nt < 8; nt++)
                tm = fmaxf(tm, fmaxf(sc[nt][i0], sc[nt][i0 + 1]));
            tm = fmaxf(tm, __shfl_xor_sync(0xffffffffu, tm, 1));
            tm = fmaxf(tm, __shfl_xor_sync(0xffffffffu, tm, 2));
            if (tm > m_i[hh]) {
                float corr = fexp2((m_i[hh] - tm) * SCL2);
                m_i[hh] = tm;
                l_i[hh] *= corr;
#pragma unroll
                for (int nt = 0; nt < 8; nt++) {
                    of[nt][i0]     *= corr;
                    of[nt][i0 + 1] *= corr;
                }
            }
            const float nm = m_i[hh];
            float rs = 0.0f;
#pragma unroll
            for (int nt = 0; nt < 8; nt++) {
                float p0 = fexp2((sc[nt][i0]     - nm) * SCL2);
                float p1 = fexp2((sc[nt][i0 + 1] - nm) * SCL2);
                rs += p0 + p1;
                Pw[row * AS + nt * 8 + 2 * tig    ] = __float_as_uint(p0);
                Pw[row * AS + nt * 8 + 2 * tig + 1] = __float_as_uint(p1);
            }
            rs += __shfl_xor_sync(0xffffffffu, rs, 1);
            rs += __shfl_xor_sync(0xffffffffu, rs, 2);
            l_i[hh] += rs;
        }
        __syncwarp();

        // ---- wait V_kt, then PV ----
        if (more) cp_wait<1>(); else cp_wait<0>();
        __syncthreads();   // S2: V_kt visible to all

#pragma unroll
        for (int ks = 0; ks < 8; ks++) {
            uint32_t af[4];
            const uint32_t* pr0 = Pw + g * AS + ks * 8;
            const uint32_t* pr1 = pr0 + 8 * AS;
            af[0] = pr0[tig];
            af[1] = pr1[tig];
            af[2] = pr0[tig + 4];
            af[3] = pr1[tig + 4];
#pragma unroll
            for (int nt = 0; nt < 8; nt++) {
                uint32_t bf[2];
                bf[0] = Vs[(ks * 8 + tig    ) * AS + nt * 8 + g];
                bf[1] = Vs[(ks * 8 + tig + 4) * AS + nt * 8 + g];
                mma_tf32(of[nt], af, bf);
            }
        }

        // ---- release Vs, prefetch next V (overlaps next scores) ----
        cp_wait<0>();      // K_next done locally
        __syncthreads();   // S3: all done PV; K_next + next Ms visible
        if (more) {
#pragma unroll
            for (int it = 0; it < 4; it++) {
                int c = tid + it * 256;
                int r = c >> 4, c4 = (c & 15) * 4;
                cp16(Vs + r * AS + c4, v + (size_t)(n1 + r) * D_MODEL + colh + c4);
            }
            cp_commit();   // pending: {V_next}
        }
    }

    // ---- epilogue ----
    const float inv0 = 1.0f / l_i[0];
    const float inv1 = 1.0f / l_i[1];
    const int r0 = m0 + wq0 + g;
    const int r1 = r0 + 8;
#pragma unroll
    for (int nt = 0; nt < 8; nt++) {
        const size_t col = colh + nt * 8 + 2 * tig;
        float2 v0 = { of[nt][0] * inv0, of[nt][1] * inv0 };
        float2 v1 = { of[nt][2] * inv1, of[nt][3] * inv1 };
        *(float2*)(ctx + (size_t)r0 * D_MODEL + col) = v0;
        *(float2*)(ctx + (size_t)r1 * D_MODEL + col) = v1;
    }
}

// ---------------------------------------------------------------------------
// LayerNorm kernels (unchanged)
// ---------------------------------------------------------------------------
__device__ __forceinline__ float block_reduce_sum(float val, float* red)
{
#pragma unroll
    for (int o = 16; o > 0; o >>= 1)
        val += __shfl_xor_sync(0xffffffffu, val, o);
    int warp = threadIdx.x >> 5;
    if ((threadIdx.x & 31) == 0) red[warp] = val;
    __syncthreads();
    if (threadIdx.x < 32) {
        float v = (threadIdx.x < 8) ? red[threadIdx.x] : 0.0f;
#pragma unroll
        for (int o = 4; o > 0; o >>= 1)
            v += __shfl_xor_sync(0xffffffffu, v, o);
        if (threadIdx.x == 0) red[0] = v;
    }
    __syncthreads();
    float r = red[0];
    __syncthreads();
    return r;
}

__global__ void __launch_bounds__(256)
ln_kernel(const float* __restrict__ in, const float* __restrict__ g,
          const float* __restrict__ bb, float eps, float* __restrict__ out)
{
    __shared__ float red[8];
    const int row = blockIdx.x;
    const float* rp = in + (size_t)row * D_MODEL;
    float vloc[4];
    float s = 0.0f;
#pragma unroll
    for (int i = 0; i < 4; i++) {
        vloc[i] = rp[threadIdx.x + i * 256];
        s += vloc[i];
    }
    float mean = block_reduce_sum(s, red) * (1.0f / D_MODEL);
    float vs = 0.0f;
#pragma unroll
    for (int i = 0; i < 4; i++) {
        float dv = vloc[i] - mean;
        vs += dv * dv;
    }
    float var  = block_reduce_sum(vs, red) * (1.0f / D_MODEL);
    float rstd = rsqrtf(var + eps);
#pragma unroll
    for (int i = 0; i < 4; i++) {
        int c = threadIdx.x + i * 256;
        out[(size_t)row * D_MODEL + c] = (vloc[i] - mean) * rstd * g[c] + bb[c];
    }
}

__global__ void __launch_bounds__(256)
ln2_fuse_kernel(const float* __restrict__ t2, const float* __restrict__ x1,
                const float* __restrict__ lnf_g, const float* __restrict__ lnf_b,
                const float* __restrict__ ln2_g, const float* __restrict__ ln2_b,
                float* __restrict__ out)
{
    __shared__ float red[8];
    const int row = blockIdx.x;
    const float* tp = t2 + (size_t)row * D_MODEL;
    const float* xp = x1 + (size_t)row * D_MODEL;
    float tv[4], xv[4];
    float s = 0.0f;
#pragma unroll
    for (int i = 0; i < 4; i++) {
        int c = threadIdx.x + i * 256;
        tv[i] = tp[c];
        xv[i] = xp[c];
        s += tv[i];
    }
    float mean1 = block_reduce_sum(s, red) * (1.0f / D_MODEL);
    float vs = 0.0f;
#pragma unroll
    for (int i = 0; i < 4; i++) {
        float dv = tv[i] - mean1;
        vs += dv * dv;
    }
    float var1  = block_reduce_sum(vs, red) * (1.0f / D_MODEL);
    float rstd1 = rsqrtf(var1 + 1e-12f);

    float u[4];
    float s2 = 0.0f;
#pragma unroll
    for (int i = 0; i < 4; i++) {
        int c = threadIdx.x + i * 256;
        float ff = (tv[i] - mean1) * rstd1 * lnf_g[c] + lnf_b[c];
        u[i] = xv[i] + ff;
        s2 += u[i];
    }
    float mean2 = block_reduce_sum(s2, red) * (1.0f / D_MODEL);
    float vs2 = 0.0f;
#pragma unroll
    for (int i = 0; i < 4; i++) {
        float dv = u[i] - mean2;
        vs2 += dv * dv;
    }
    float var2  = block_reduce_sum(vs2, red) * (1.0f / D_MODEL);
    float rstd2 = rsqrtf(var2 + 1e-5f);
#pragma unroll
    for (int i = 0; i < 4; i++) {
        int c = threadIdx.x + i * 256;
        out[(size_t)row * D_MODEL + c] = (u[i] - mean2) * rstd2 * ln2_g[c] + ln2_b[c];
    }
}

// ---------------------------------------------------------------------------
// Launcher
// ---------------------------------------------------------------------------
extern "C" void kernel_launch(void* const* d_in, const int* in_sizes, int n_in,
                              void* d_out, int out_size)
{
    const float* x      = (const float*)d_in[0];
    const int*   mask   = (const int*)  d_in[1];
    const float* wq     = (const float*)d_in[2];
    const float* bq     = (const float*)d_in[3];
    const float* wk     = (const float*)d_in[4];
    const float* bk     = (const float*)d_in[5];
    const float* wv     = (const float*)d_in[6];
    const float* bv     = (const float*)d_in[7];
    const float* wo     = (const float*)d_in[8];
    const float* bo     = (const float*)d_in[9];
    const float* ln1_g  = (const float*)d_in[10];
    const float* ln1_b  = (const float*)d_in[11];
    const float* w1     = (const float*)d_in[12];
    const float* b1     = (const float*)d_in[13];
    const float* w2     = (const float*)d_in[14];
    const float* b2     = (const float*)d_in[15];
    const float* lnf_g  = (const float*)d_in[16];
    const float* lnf_b  = (const float*)d_in[17];
    const float* ln2_g  = (const float*)d_in[18];
    const float* ln2_b  = (const float*)d_in[19];
    float* out = (float*)d_out;

    float *q, *k, *v, *ctx, *t, *x1, *h;
    cudaGetSymbolAddress((void**)&q,   g_q);
    cudaGetSymbolAddress((void**)&k,   g_k);
    cudaGetSymbolAddress((void**)&v,   g_v);
    cudaGetSymbolAddress((void**)&ctx, g_ctx);
    cudaGetSymbolAddress((void**)&t,   g_t);
    cudaGetSymbolAddress((void**)&x1,  g_x1);
    cudaGetSymbolAddress((void**)&h,   g_h);

    cudaFuncSetAttribute(gemm_tf32_kernel<0>,
                         cudaFuncAttributeMaxDynamicSharedMemorySize, GEMM_SMEM);
    cudaFuncSetAttribute(gemm_tf32_kernel<1>,
                         cudaFuncAttributeMaxDynamicSharedMemorySize, GEMM_SMEM);
    cudaFuncSetAttribute(gemm_tf32_kernel<2>,
                         cudaFuncAttributeMaxDynamicSharedMemorySize, GEMM_SMEM);
    cudaFuncSetAttribute(attn_mma_kernel,
                         cudaFuncAttributeMaxDynamicSharedMemorySize, ATTN_SMEM);

    // QKV projections
    gemm_tf32_kernel<0><<<dim3(D_MODEL / 128, MROWS / 128), 256, GEMM_SMEM>>>(
        x, wq, bq, nullptr, q, MROWS, D_MODEL, D_MODEL);
    gemm_tf32_kernel<0><<<dim3(D_MODEL / 128, MROWS / 128), 256, GEMM_SMEM>>>(
        x, wk, bk, nullptr, k, MROWS, D_MODEL, D_MODEL);
    gemm_tf32_kernel<0><<<dim3(D_MODEL / 128, MROWS / 128), 256, GEMM_SMEM>>>(
        x, wv, bv, nullptr, v, MROWS, D_MODEL, D_MODEL);

    // attention
    attn_mma_kernel<<<dim3(SEQ / 128, BATCH * NHEAD), 256, ATTN_SMEM>>>(
        q, k, v, mask, ctx);

    // output projection + residual, then LN1
    gemm_tf32_kernel<1><<<dim3(D_MODEL / 128, MROWS / 128), 256, GEMM_SMEM>>>(
        ctx, wo, bo, x, t, MROWS, D_MODEL, D_MODEL);
    ln_kernel<<<MROWS, 256>>>(t, ln1_g, ln1_b, 1e-5f, x1);

    // FFN
    gemm_tf32_kernel<2><<<dim3(FFDIM / 128, MROWS / 128), 256, GEMM_SMEM>>>(
        x1, w1, b1, nullptr, h, MROWS, FFDIM, D_MODEL);
    gemm_tf32_kernel<1><<<dim3(D_MODEL / 128, MROWS / 128), 256, GEMM_SMEM>>>(
        h, w2, b2, x1, t, MROWS, D_MODEL, FFDIM);

    // fused double LayerNorm epilogue
    ln2_fuse_kernel<<<MROWS, 256>>>(t, x1, lnf_g, lnf_b, ln2_g, ln2_b, out);
}

// round 7
// speedup vs baseline: 3.9019x; 1.0701x over previous
#include <cuda_runtime.h>
#include <math.h>
#include <stdint.h>

// ---------------------------------------------------------------------------
// Problem constants (fixed shapes)
// ---------------------------------------------------------------------------
#define D_MODEL 1024
#define NHEAD   16
#define HDIM    64
#define FFDIM   4096
#define BATCH   2
#define SEQ     2048
#define MROWS   (BATCH * SEQ)   // 4096

// ---------------------------------------------------------------------------
// Scratch (device globals; no allocation allowed)
// ---------------------------------------------------------------------------
__device__ float g_q  [MROWS * D_MODEL];
__device__ float g_k  [MROWS * D_MODEL];
__device__ float g_v  [MROWS * D_MODEL];
__device__ float g_ctx[MROWS * D_MODEL];
__device__ float g_t  [MROWS * D_MODEL];
__device__ float g_x1 [MROWS * D_MODEL];
__device__ float g_h  [MROWS * FFDIM];

// ---------------------------------------------------------------------------
// helpers
// ---------------------------------------------------------------------------
__device__ __forceinline__ void mma_tf32(float* c, const uint32_t* a, const uint32_t* b) {
    asm volatile(
        "mma.sync.aligned.m16n8k8.row.col.f32.tf32.tf32.f32 "
        "{%0,%1,%2,%3}, {%4,%5,%6,%7}, {%8,%9}, {%0,%1,%2,%3};"
        : "+f"(c[0]), "+f"(c[1]), "+f"(c[2]), "+f"(c[3])
        : "r"(a[0]), "r"(a[1]), "r"(a[2]), "r"(a[3]), "r"(b[0]), "r"(b[1]));
}

__device__ __forceinline__ void cp16(const void* dst, const void* src) {
    uint32_t d = (uint32_t)__cvta_generic_to_shared(dst);
    asm volatile("cp.async.cg.shared.global [%0], [%1], 16;" :: "r"(d), "l"(src));
}
__device__ __forceinline__ void cp_commit() {
    asm volatile("cp.async.commit_group;");
}
template <int N> __device__ __forceinline__ void cp_wait() {
    asm volatile("cp.async.wait_group %0;" :: "n"(N));
}

__device__ __forceinline__ float fexp2(float x) {
    float r;
    asm("ex2.approx.ftz.f32 %0, %1;" : "=f"(r) : "f"(x));
    return r;
}

// ---------------------------------------------------------------------------
// tf32 tensor-core GEMM body, 3-stage cp.async pipeline (validated R6).
// C[bm:bm+128, bn:bn+128] = A @ W + bias (+ epilogue)
// ---------------------------------------------------------------------------
#define AST 36
#define BST 136
#define STG_A (128 * AST)
#define STG_B (32 * BST)
#define GEMM_SMEM ((3 * STG_A + 3 * STG_B) * 4)

template <int EPI>
__device__ __forceinline__ void gemm_body(
    const float* __restrict__ A, const float* __restrict__ W,
    const float* __restrict__ bias, const float* __restrict__ res,
    float* __restrict__ C, int M, int N, int K, int bm, int bn, uint32_t* smg)
{
    uint32_t* As = smg;
    uint32_t* Bs = smg + 3 * STG_A;

    const int tid     = threadIdx.x;
    const int lane    = tid & 31;
    const int warp_id = tid >> 5;
    const int g       = lane >> 2;
    const int tig     = lane & 3;
    const int wm      = (warp_id >> 2) * 64;
    const int wn      = (warp_id & 3) * 32;

    int am[4], ac[4], bk[4], bnc[4];
#pragma unroll
    for (int it = 0; it < 4; it++) {
        int c = tid + it * 256;
        am[it]  = c >> 3;
        ac[it]  = (c & 7) * 4;
        bk[it]  = c >> 5;
        bnc[it] = (c & 31) * 4;
    }

    float acc[4][4][4];
#pragma unroll
    for (int i = 0; i < 4; i++)
#pragma unroll
        for (int j = 0; j < 4; j++)
#pragma unroll
            for (int r = 0; r < 4; r++) acc[i][j][r] = 0.0f;

    const int KT = K >> 5;

#pragma unroll
    for (int s = 0; s < 2; s++) {
        const int k0 = s << 5;
#pragma unroll
        for (int it = 0; it < 4; it++) {
            cp16(As + s * STG_A + am[it] * AST + ac[it],
                 A + (size_t)(bm + am[it]) * K + k0 + ac[it]);
            cp16(Bs + s * STG_B + bk[it] * BST + bnc[it],
                 W + (size_t)(k0 + bk[it]) * N + bn + bnc[it]);
        }
        cp_commit();
    }

    int cur = 0;
    for (int kt = 0; kt < KT; kt++) {
        if (kt + 2 < KT) cp_wait<1>(); else cp_wait<0>();
        __syncthreads();

        if (kt + 2 < KT) {
            int nb = cur + 2;
            if (nb >= 3) nb -= 3;
            const int k0 = (kt + 2) << 5;
#pragma unroll
            for (int it = 0; it < 4; it++) {
                cp16(As + nb * STG_A + am[it] * AST + ac[it],
                     A + (size_t)(bm + am[it]) * K + k0 + ac[it]);
                cp16(Bs + nb * STG_B + bk[it] * BST + bnc[it],
                     W + (size_t)(k0 + bk[it]) * N + bn + bnc[it]);
            }
            cp_commit();
        }

        const uint32_t* Ac = As + cur * STG_A;
        const uint32_t* Bc = Bs + cur * STG_B;
#pragma unroll
        for (int ks = 0; ks < 4; ks++) {
            const int kb = ks * 8;
            uint32_t af[4][4];
#pragma unroll
            for (int mt = 0; mt < 4; mt++) {
                const uint32_t* ar0 = Ac + (wm + mt * 16 + g) * AST + kb;
                const uint32_t* ar1 = ar0 + 8 * AST;
                af[mt][0] = ar0[tig];
                af[mt][1] = ar1[tig];
                af[mt][2] = ar0[tig + 4];
                af[mt][3] = ar1[tig + 4];
            }
            uint32_t bf[4][2];
#pragma unroll
            for (int nt = 0; nt < 4; nt++) {
                const int nb2 = wn + nt * 8 + g;
                bf[nt][0] = Bc[(kb + tig    ) * BST + nb2];
                bf[nt][1] = Bc[(kb + tig + 4) * BST + nb2];
            }
#pragma unroll
            for (int mt = 0; mt < 4; mt++)
#pragma unroll
                for (int nt = 0; nt < 4; nt++)
                    mma_tf32(acc[mt][nt], af[mt], bf[nt]);
        }
        cur++;
        if (cur >= 3) cur -= 3;
    }

#pragma unroll
    for (int mt = 0; mt < 4; mt++) {
        const int r0 = bm + wm + mt * 16 + g;
        const int r1 = r0 + 8;
#pragma unroll
        for (int nt = 0; nt < 4; nt++) {
            const int col = bn + wn + nt * 8 + tig * 2;
            float2 bv = *(const float2*)(bias + col);
            float2 v0, v1;
            v0.x = acc[mt][nt][0] + bv.x;
            v0.y = acc[mt][nt][1] + bv.y;
            v1.x = acc[mt][nt][2] + bv.x;
            v1.y = acc[mt][nt][3] + bv.y;
            if (EPI == 1) {
                float2 ra = *(const float2*)(res + (size_t)r0 * N + col);
                float2 rb = *(const float2*)(res + (size_t)r1 * N + col);
                v0.x += ra.x; v0.y += ra.y;
                v1.x += rb.x; v1.y += rb.y;
            }
            if (EPI == 2) {
                v0.x = 0.5f * v0.x * (1.0f + erff(v0.x * 0.70710678118654752f));
                v0.y = 0.5f * v0.y * (1.0f + erff(v0.y * 0.70710678118654752f));
                v1.x = 0.5f * v1.x * (1.0f + erff(v1.x * 0.70710678118654752f));
                v1.y = 0.5f * v1.y * (1.0f + erff(v1.y * 0.70710678118654752f));
            }
            *(float2*)(C + (size_t)r0 * N + col) = v0;
            *(float2*)(C + (size_t)r1 * N + col) = v1;
        }
    }
}

template <int EPI>
__global__ void __launch_bounds__(256)
gemm_tf32_kernel(const float* __restrict__ A, const float* __restrict__ W,
                 const float* __restrict__ bias, const float* __restrict__ res,
                 float* __restrict__ C, int M, int N, int K)
{
    extern __shared__ uint32_t smg[];
    gemm_body<EPI>(A, W, bias, res, C, M, N, K,
                   blockIdx.y * 128, blockIdx.x * 128, smg);
}

// Fused QKV projection: grid.x = 24 (3 matrices x 8 col-blocks)
__global__ void __launch_bounds__(256)
gemm_qkv_kernel(const float* __restrict__ x,
                const float* __restrict__ wq, const float* __restrict__ bq, float* q,
                const float* __restrict__ wk, const float* __restrict__ bk, float* k,
                const float* __restrict__ wv, const float* __restrict__ bv, float* v)
{
    extern __shared__ uint32_t smg[];
    const int which = blockIdx.x >> 3;
    const int bn    = (blockIdx.x & 7) * 128;
    const float* W  = (which == 0) ? wq : (which == 1) ? wk : wv;
    const float* B  = (which == 0) ? bq : (which == 1) ? bk : bv;
    float*       C  = (which == 0) ? q  : (which == 1) ? k  : v;
    gemm_body<0>(x, W, B, nullptr, C, MROWS, D_MODEL, D_MODEL,
                 blockIdx.y * 128, bn, smg);
}

// ---------------------------------------------------------------------------
// Tensor-core flash attention, LDS-optimized:
// BQ=128, BK=64, HD=64. 128 threads = 4 warps; each warp owns 32 q rows
// (2 m16 tiles). Q fragments held in registers (loaded once). Scores computed
// in two 32-key halves so both m-tiles share one K B-fragment load.
// K/V cp.async software pipeline as in R6.
// ---------------------------------------------------------------------------
#define AS 68   // smem row stride (4 mod 32 -> conflict-free mma frag LDS)
#define ATTN_SMEM ((64 * AS + 64 * AS + 128 * AS) * 4 + 64 * 4)
#define NT (SEQ / 64)

__global__ void __launch_bounds__(128)
attn_mma_kernel(const float* __restrict__ q, const float* __restrict__ k,
                const float* __restrict__ v, const int* __restrict__ mask,
                float* __restrict__ ctx)
{
    extern __shared__ uint32_t sm[];
    uint32_t* Ks = sm;                    // [64][AS]
    uint32_t* Vs = Ks + 64 * AS;          // [64][AS]
    uint32_t* Ps = Vs + 64 * AS;          // 4 warps x [32][AS]; also Q staging [128][AS]
    int*      Ms = (int*)(Ps + 128 * AS); // 64

    const int tid  = threadIdx.x;
    const int lane = tid & 31;
    const int wid  = tid >> 5;            // 0..3
    const int g    = lane >> 2;
    const int tig  = lane & 3;
    const int b    = blockIdx.y >> 4;
    const int h    = blockIdx.y & 15;
    const int m0   = b * SEQ + blockIdx.x * 128;
    const size_t colh = (size_t)h * HDIM;
    uint32_t* Pw  = Ps + wid * 32 * AS;
    const int wq0 = wid * 32;
    const float SCL2 = 0.125f * 1.44269504088896340736f;  // (1/sqrt(64))*log2(e)

    // ---- prologue: stage Q into Ps region; K0; V0 ----
#pragma unroll
    for (int it = 0; it < 16; it++) {
        int c = tid + it * 128;           // 0..2047
        int r = c >> 4, c4 = (c & 15) * 4;
        cp16(Ps + r * AS + c4, q + (size_t)(m0 + r) * D_MODEL + colh + c4);
    }
#pragma unroll
    for (int it = 0; it < 8; it++) {
        int c = tid + it * 128;           // 0..1023
        int r = c >> 4, c4 = (c & 15) * 4;
        cp16(Ks + r * AS + c4, k + (size_t)(b * SEQ + r) * D_MODEL + colh + c4);
    }
    cp_commit();   // group {Q, K0}
#pragma unroll
    for (int it = 0; it < 8; it++) {
        int c = tid + it * 128;
        int r = c >> 4, c4 = (c & 15) * 4;
        cp16(Vs + r * AS + c4, v + (size_t)(b * SEQ + r) * D_MODEL + colh + c4);
    }
    cp_commit();   // group {V0}
    if (tid < 64) Ms[tid] = mask[b * SEQ + tid];

    cp_wait<1>();      // Q + K0 arrived (pending: V0)
    __syncthreads();

    // ---- load Q fragments into registers (once) ----
    uint32_t qf[2][8][4];
#pragma unroll
    for (int mt = 0; mt < 2; mt++)
#pragma unroll
        for (int ks = 0; ks < 8; ks++) {
            const uint32_t* r0 = Ps + (wq0 + mt * 16 + g) * AS + ks * 8;
            const uint32_t* r1 = r0 + 8 * AS;
            qf[mt][ks][0] = r0[tig];
            qf[mt][ks][1] = r1[tig];
            qf[mt][ks][2] = r0[tig + 4];
            qf[mt][ks][3] = r1[tig + 4];
        }
    __syncthreads();   // everyone done reading Q staging (P reuses it)

    float m_i[2][2], l_i[2][2];
#pragma unroll
    for (int mt = 0; mt < 2; mt++) {
        m_i[mt][0] = -3.0e38f; m_i[mt][1] = -3.0e38f;
        l_i[mt][0] = 0.0f;     l_i[mt][1] = 0.0f;
    }
    float of[2][8][4];
#pragma unroll
    for (int mt = 0; mt < 2; mt++)
#pragma unroll
        for (int nt = 0; nt < 8; nt++)
#pragma unroll
            for (int r = 0; r < 4; r++) of[mt][nt][r] = 0.0f;

    for (int kt = 0; kt < NT; kt++) {
        const bool more = (kt + 1 < NT);
        const int n1 = b * SEQ + (kt + 1) * 64;

        // ---- scores + softmax, two 32-key halves ----
#pragma unroll
        for (int half = 0; half < 2; half++) {
            float sc[2][4][4];
#pragma unroll
            for (int mt = 0; mt < 2; mt++)
#pragma unroll
                for (int n = 0; n < 4; n++)
#pragma unroll
                    for (int r = 0; r < 4; r++) sc[mt][n][r] = 0.0f;

#pragma unroll
            for (int ks = 0; ks < 8; ks++) {
                uint32_t bf[4][2];
#pragma unroll
                for (int n = 0; n < 4; n++) {
                    const uint32_t* kr = Ks + (half * 32 + n * 8 + g) * AS + ks * 8;
                    bf[n][0] = kr[tig];
                    bf[n][1] = kr[tig + 4];
                }
#pragma unroll
                for (int mt = 0; mt < 2; mt++)
#pragma unroll
                    for (int n = 0; n < 4; n++)
                        mma_tf32(sc[mt][n], qf[mt][ks], bf[n]);
            }

            // mask
#pragma unroll
            for (int n = 0; n < 4; n++) {
                int c0 = half * 32 + n * 8 + 2 * tig;
                if (Ms[c0] == 0) {
#pragma unroll
                    for (int mt = 0; mt < 2; mt++) { sc[mt][n][0] = -1e9f; sc[mt][n][2] = -1e9f; }
                }
                if (Ms[c0 + 1] == 0) {
#pragma unroll
                    for (int mt = 0; mt < 2; mt++) { sc[mt][n][1] = -1e9f; sc[mt][n][3] = -1e9f; }
                }
            }

            // online softmax (per m-tile, per row-half)
#pragma unroll
            for (int mt = 0; mt < 2; mt++) {
#pragma unroll
                for (int hh = 0; hh < 2; hh++) {
                    const int i0  = hh * 2;
                    const int row = mt * 16 + (hh ? (g + 8) : g);
                    float tm = -3.0e38f;
#pragma unroll
                    for (int n = 0; n < 4; n++)
                        tm = fmaxf(tm, fmaxf(sc[mt][n][i0], sc[mt][n][i0 + 1]));
                    tm = fmaxf(tm, __shfl_xor_sync(0xffffffffu, tm, 1));
                    tm = fmaxf(tm, __shfl_xor_sync(0xffffffffu, tm, 2));
                    if (tm > m_i[mt][hh]) {
                        float corr = fexp2((m_i[mt][hh] - tm) * SCL2);
                        m_i[mt][hh] = tm;
                        l_i[mt][hh] *= corr;
#pragma unroll
                        for (int nt = 0; nt < 8; nt++) {
                            of[mt][nt][i0]     *= corr;
                            of[mt][nt][i0 + 1] *= corr;
                        }
                    }
                    const float nm = m_i[mt][hh];
                    float rs = 0.0f;
#pragma unroll
                    for (int n = 0; n < 4; n++) {
                        float p0 = fexp2((sc[mt][n][i0]     - nm) * SCL2);
                        float p1 = fexp2((sc[mt][n][i0 + 1] - nm) * SCL2);
                        rs += p0 + p1;
                        Pw[row * AS + half * 32 + n * 8 + 2 * tig    ] = __float_as_uint(p0);
                        Pw[row * AS + half * 32 + n * 8 + 2 * tig + 1] = __float_as_uint(p1);
                    }
                    rs += __shfl_xor_sync(0xffffffffu, rs, 1);
                    rs += __shfl_xor_sync(0xffffffffu, rs, 2);
                    l_i[mt][hh] += rs;
                }
            }
        }
        __syncwarp();

        __syncthreads();   // S1: all warps done reading Ks & Ms

        // ---- prefetch next K (overlaps V-wait + PV) ----
        if (more) {
#pragma unroll
            for (int it = 0; it < 8; it++) {
                int c = tid + it * 128;
                int r = c >> 4, c4 = (c & 15) * 4;
                cp16(Ks + r * AS + c4, k + (size_t)(n1 + r) * D_MODEL + colh + c4);
            }
            cp_commit();   // pending: {V_kt, K_next}
            if (tid < 64) Ms[tid] = mask[n1 + tid];
        }

        if (more) cp_wait<1>(); else cp_wait<0>();
        __syncthreads();   // S2: V_kt visible

        // ---- O += P @ V ----
#pragma unroll
        for (int ks = 0; ks < 8; ks++) {
            uint32_t bfv[8][2];
#pragma unroll
            for (int nt = 0; nt < 8; nt++) {
                bfv[nt][0] = Vs[(ks * 8 + tig    ) * AS + nt * 8 + g];
                bfv[nt][1] = Vs[(ks * 8 + tig + 4) * AS + nt * 8 + g];
            }
#pragma unroll
            for (int mt = 0; mt < 2; mt++) {
                uint32_t af[4];
                const uint32_t* p0p = Pw + (mt * 16 + g) * AS + ks * 8;
                const uint32_t* p1p = p0p + 8 * AS;
                af[0] = p0p[tig];
                af[1] = p1p[tig];
                af[2] = p0p[tig + 4];
                af[3] = p1p[tig + 4];
#pragma unroll
                for (int nt = 0; nt < 8; nt++)
                    mma_tf32(of[mt][nt], af, bfv[nt]);
            }
        }

        cp_wait<0>();      // K_next arrived
        __syncthreads();   // S3: all done PV; K_next + Ms visible
        if (more) {
#pragma unroll
            for (int it = 0; it < 8; it++) {
                int c = tid + it * 128;
                int r = c >> 4, c4 = (c & 15) * 4;
                cp16(Vs + r * AS + c4, v + (size_t)(n1 + r) * D_MODEL + colh + c4);
            }
            cp_commit();   // pending: {V_next}
        }
    }

    // ---- epilogue ----
#pragma unroll
    for (int mt = 0; mt < 2; mt++) {
        const float inv0 = 1.0f / l_i[mt][0];
        const float inv1 = 1.0f / l_i[mt][1];
        const int r0 = m0 + wq0 + mt * 16 + g;
        const int r1 = r0 + 8;
#pragma unroll
        for (int nt = 0; nt < 8; nt++) {
            const size_t col = colh + nt * 8 + 2 * tig;
            float2 v0 = { of[mt][nt][0] * inv0, of[mt][nt][1] * inv0 };
            float2 v1 = { of[mt][nt][2] * inv1, of[mt][nt][3] * inv1 };
            *(float2*)(ctx + (size_t)r0 * D_MODEL + col) = v0;
            *(float2*)(ctx + (size_t)r1 * D_MODEL + col) = v1;
        }
    }
}

// ---------------------------------------------------------------------------
// LayerNorm kernels (unchanged)
// ---------------------------------------------------------------------------
__device__ __forceinline__ float block_reduce_sum(float val, float* red)
{
#pragma unroll
    for (int o = 16; o > 0; o >>= 1)
        val += __shfl_xor_sync(0xffffffffu, val, o);
    int warp = threadIdx.x >> 5;
    if ((threadIdx.x & 31) == 0) red[warp] = val;
    __syncthreads();
    if (threadIdx.x < 32) {
        float v = (threadIdx.x < 8) ? red[threadIdx.x] : 0.0f;
#pragma unroll
        for (int o = 4; o > 0; o >>= 1)
            v += __shfl_xor_sync(0xffffffffu, v, o);
        if (threadIdx.x == 0) red[0] = v;
    }
    __syncthreads();
    float r = red[0];
    __syncthreads();
    return r;
}

__global__ void __launch_bounds__(256)
ln_kernel(const float* __restrict__ in, const float* __restrict__ g,
          const float* __restrict__ bb, float eps, float* __restrict__ out)
{
    __shared__ float red[8];
    const int row = blockIdx.x;
    const float* rp = in + (size_t)row * D_MODEL;
    float vloc[4];
    float s = 0.0f;
#pragma unroll
    for (int i = 0; i < 4; i++) {
        vloc[i] = rp[threadIdx.x + i * 256];
        s += vloc[i];
    }
    float mean = block_reduce_sum(s, red) * (1.0f / D_MODEL);
    float vs = 0.0f;
#pragma unroll
    for (int i = 0; i < 4; i++) {
        float dv = vloc[i] - mean;
        vs += dv * dv;
    }
    float var  = block_reduce_sum(vs, red) * (1.0f / D_MODEL);
    float rstd = rsqrtf(var + eps);
#pragma unroll
    for (int i = 0; i < 4; i++) {
        int c = threadIdx.x + i * 256;
        out[(size_t)row * D_MODEL + c] = (vloc[i] - mean) * rstd * g[c] + bb[c];
    }
}

__global__ void __launch_bounds__(256)
ln2_fuse_kernel(const float* __restrict__ t2, const float* __restrict__ x1,
                const float* __restrict__ lnf_g, const float* __restrict__ lnf_b,
                const float* __restrict__ ln2_g, const float* __restrict__ ln2_b,
                float* __restrict__ out)
{
    __shared__ float red[8];
    const int row = blockIdx.x;
    const float* tp = t2 + (size_t)row * D_MODEL;
    const float* xp = x1 + (size_t)row * D_MODEL;
    float tv[4], xv[4];
    float s = 0.0f;
#pragma unroll
    for (int i = 0; i < 4; i++) {
        int c = threadIdx.x + i * 256;
        tv[i] = tp[c];
        xv[i] = xp[c];
        s += tv[i];
    }
    float mean1 = block_reduce_sum(s, red) * (1.0f / D_MODEL);
    float vs = 0.0f;
#pragma unroll
    for (int i = 0; i < 4; i++) {
        float dv = tv[i] - mean1;
        vs += dv * dv;
    }
    float var1  = block_reduce_sum(vs, red) * (1.0f / D_MODEL);
    float rstd1 = rsqrtf(var1 + 1e-12f);

    float u[4];
    float s2 = 0.0f;
#pragma unroll
    for (int i = 0; i < 4; i++) {
        int c = threadIdx.x + i * 256;
        float ff = (tv[i] - mean1) * rstd1 * lnf_g[c] + lnf_b[c];
        u[i] = xv[i] + ff;
        s2 += u[i];
    }
    float mean2 = block_reduce_sum(s2, red) * (1.0f / D_MODEL);
    float vs2 = 0.0f;
#pragma unroll
    for (int i = 0; i < 4; i++) {
        float dv = u[i] - mean2;
        vs2 += dv * dv;
    }
    float var2  = block_reduce_sum(vs2, red) * (1.0f / D_MODEL);
    float rstd2 = rsqrtf(var2 + 1e-5f);
#pragma unroll
    for (int i = 0; i < 4; i++) {
        int c = threadIdx.x + i * 256;
        out[(size_t)row * D_MODEL + c] = (u[i] - mean2) * rstd2 * ln2_g[c] + ln2_b[c];
    }
}

// ---------------------------------------------------------------------------
// Launcher
// ---------------------------------------------------------------------------
extern "C" void kernel_launch(void* const* d_in, const int* in_sizes, int n_in,
                              void* d_out, int out_size)
{
    const float* x      = (const float*)d_in[0];
    const int*   mask   = (const int*)  d_in[1];
    const float* wq     = (const float*)d_in[2];
    const float* bq     = (const float*)d_in[3];
    const float* wk     = (const float*)d_in[4];
    const float* bk     = (const float*)d_in[5];
    const float* wv     = (const float*)d_in[6];
    const float* bv     = (const float*)d_in[7];
    const float* wo     = (const float*)d_in[8];
    const float* bo     = (const float*)d_in[9];
    const float* ln1_g  = (const float*)d_in[10];
    const float* ln1_b  = (const float*)d_in[11];
    const float* w1     = (const float*)d_in[12];
    const float* b1     = (const float*)d_in[13];
    const float* w2     = (const float*)d_in[14];
    const float* b2     = (const float*)d_in[15];
    const float* lnf_g  = (const float*)d_in[16];
    const float* lnf_b  = (const float*)d_in[17];
    const float* ln2_g  = (const float*)d_in[18];
    const float* ln2_b  = (const float*)d_in[19];
    float* out = (float*)d_out;

    float *q, *k, *v, *ctx, *t, *x1, *h;
    cudaGetSymbolAddress((void**)&q,   g_q);
    cudaGetSymbolAddress((void**)&k,   g_k);
    cudaGetSymbolAddress((void**)&v,   g_v);
    cudaGetSymbolAddress((void**)&ctx, g_ctx);
    cudaGetSymbolAddress((void**)&t,   g_t);
    cudaGetSymbolAddress((void**)&x1,  g_x1);
    cudaGetSymbolAddress((void**)&h,   g_h);

    cudaFuncSetAttribute(gemm_qkv_kernel,
                         cudaFuncAttributeMaxDynamicSharedMemorySize, GEMM_SMEM);
    cudaFuncSetAttribute(gemm_tf32_kernel<1>,
                         cudaFuncAttributeMaxDynamicSharedMemorySize, GEMM_SMEM);
    cudaFuncSetAttribute(gemm_tf32_kernel<2>,
                         cudaFuncAttributeMaxDynamicSharedMemorySize, GEMM_SMEM);
    cudaFuncSetAttribute(attn_mma_kernel,
                         cudaFuncAttributeMaxDynamicSharedMemorySize, ATTN_SMEM);

    // fused QKV projections
    gemm_qkv_kernel<<<dim3(24, MROWS / 128), 256, GEMM_SMEM>>>(
        x, wq, bq, q, wk, bk, k, wv, bv, v);

    // attention
    attn_mma_kernel<<<dim3(SEQ / 128, BATCH * NHEAD), 128, ATTN_SMEM>>>(
        q, k, v, mask, ctx);

    // output projection + residual, then LN1
    gemm_tf32_kernel<1><<<dim3(D_MODEL / 128, MROWS / 128), 256, GEMM_SMEM>>>(
        ctx, wo, bo, x, t, MROWS, D_MODEL, D_MODEL);
    ln_kernel<<<MROWS, 256>>>(t, ln1_g, ln1_b, 1e-5f, x1);

    // FFN
    gemm_tf32_kernel<2><<<dim3(FFDIM / 128, MROWS / 128), 256, GEMM_SMEM>>>(
        x1, w1, b1, nullptr, h, MROWS, FFDIM, D_MODEL);
    gemm_tf32_kernel<1><<<dim3(D_MODEL / 128, MROWS / 128), 256, GEMM_SMEM>>>(
        h, w2, b2, x1, t, MROWS, D_MODEL, FFDIM);

    // fused double LayerNorm epilogue
    ln2_fuse_kernel<<<MROWS, 256>>>(t, x1, lnf_g, lnf_b, ln2_g, ln2_b, out);
}

// round 8
// speedup vs baseline: 3.9680x; 1.0169x over previous
#include <cuda_runtime.h>
#include <math.h>
#include <stdint.h>

// ---------------------------------------------------------------------------
// Problem constants (fixed shapes)
// ---------------------------------------------------------------------------
#define D_MODEL 1024
#define NHEAD   16
#define HDIM    64
#define FFDIM   4096
#define BATCH   2
#define SEQ     2048
#define MROWS   (BATCH * SEQ)   // 4096

// ---------------------------------------------------------------------------
// Scratch (device globals; no allocation allowed)
// ---------------------------------------------------------------------------
__device__ float g_q  [MROWS * D_MODEL];
__device__ float g_k  [MROWS * D_MODEL];
__device__ float g_v  [MROWS * D_MODEL];
__device__ float g_ctx[MROWS * D_MODEL];
__device__ float g_t  [MROWS * D_MODEL];
__device__ float g_x1 [MROWS * D_MODEL];
__device__ float g_h  [MROWS * FFDIM];

// ---------------------------------------------------------------------------
// helpers
// ---------------------------------------------------------------------------
__device__ __forceinline__ void mma_tf32(float* c, const uint32_t* a, const uint32_t* b) {
    asm volatile(
        "mma.sync.aligned.m16n8k8.row.col.f32.tf32.tf32.f32 "
        "{%0,%1,%2,%3}, {%4,%5,%6,%7}, {%8,%9}, {%0,%1,%2,%3};"
        : "+f"(c[0]), "+f"(c[1]), "+f"(c[2]), "+f"(c[3])
        : "r"(a[0]), "r"(a[1]), "r"(a[2]), "r"(a[3]), "r"(b[0]), "r"(b[1]));
}

__device__ __forceinline__ void cp16(const void* dst, const void* src) {
    uint32_t d = (uint32_t)__cvta_generic_to_shared(dst);
    asm volatile("cp.async.cg.shared.global [%0], [%1], 16;" :: "r"(d), "l"(src));
}
__device__ __forceinline__ void cp_commit() {
    asm volatile("cp.async.commit_group;");
}
template <int N> __device__ __forceinline__ void cp_wait() {
    asm volatile("cp.async.wait_group %0;" :: "n"(N));
}

__device__ __forceinline__ float fexp2(float x) {
    float r;
    asm("ex2.approx.ftz.f32 %0, %1;" : "=f"(r) : "f"(x));
    return r;
}

// ---------------------------------------------------------------------------
// tf32 tensor-core GEMM body, 3-stage cp.async pipeline.
// CTA tile 128x128x32, 128 threads = 4 warps, warp tile 64x64
// (LDS/MMA ratio 1.0 vs 1.5 of the 8-warp 64x32 variant).
// A smem: [m][k] stride 36; B smem: [k][n] stride 136. Raw fp32 bits -> tf32.
// ---------------------------------------------------------------------------
#define AST 36
#define BST 136
#define STG_A (128 * AST)
#define STG_B (32 * BST)
#define GEMM_SMEM ((3 * STG_A + 3 * STG_B) * 4)

template <int EPI>
__device__ __forceinline__ void gemm_body(
    const float* __restrict__ A, const float* __restrict__ W,
    const float* __restrict__ bias, const float* __restrict__ res,
    float* __restrict__ C, int M, int N, int K, int bm, int bn, uint32_t* smg)
{
    uint32_t* As = smg;
    uint32_t* Bs = smg + 3 * STG_A;

    const int tid     = threadIdx.x;
    const int lane    = tid & 31;
    const int warp_id = tid >> 5;          // 0..3
    const int g       = lane >> 2;
    const int tig     = lane & 3;
    const int wm      = (warp_id >> 1) * 64;   // 0 / 64
    const int wn      = (warp_id & 1) * 64;    // 0 / 64

    float acc[4][8][4];
#pragma unroll
    for (int i = 0; i < 4; i++)
#pragma unroll
        for (int j = 0; j < 8; j++)
#pragma unroll
            for (int r = 0; r < 4; r++) acc[i][j][r] = 0.0f;

    const int KT = K >> 5;

    // prefetch stages 0,1 (each thread: 8 A-chunks + 8 B-chunks)
#pragma unroll
    for (int s = 0; s < 2; s++) {
        const int k0 = s << 5;
#pragma unroll
        for (int it = 0; it < 8; it++) {
            int c  = tid + it * 128;           // 0..1023
            int ar = c >> 3, ac4 = (c & 7) * 4;
            cp16(As + s * STG_A + ar * AST + ac4,
                 A + (size_t)(bm + ar) * K + k0 + ac4);
            int br = c >> 5, bc4 = (c & 31) * 4;
            cp16(Bs + s * STG_B + br * BST + bc4,
                 W + (size_t)(k0 + br) * N + bn + bc4);
        }
        cp_commit();
    }

    int cur = 0;
    for (int kt = 0; kt < KT; kt++) {
        if (kt + 2 < KT) cp_wait<1>(); else cp_wait<0>();
        __syncthreads();

        if (kt + 2 < KT) {
            int nb = cur + 2;
            if (nb >= 3) nb -= 3;
            const int k0 = (kt + 2) << 5;
#pragma unroll
            for (int it = 0; it < 8; it++) {
                int c  = tid + it * 128;
                int ar = c >> 3, ac4 = (c & 7) * 4;
                cp16(As + nb * STG_A + ar * AST + ac4,
                     A + (size_t)(bm + ar) * K + k0 + ac4);
                int br = c >> 5, bc4 = (c & 31) * 4;
                cp16(Bs + nb * STG_B + br * BST + bc4,
                     W + (size_t)(k0 + br) * N + bn + bc4);
            }
            cp_commit();
        }

        const uint32_t* Ac = As + cur * STG_A;
        const uint32_t* Bc = Bs + cur * STG_B;
#pragma unroll
        for (int ks = 0; ks < 4; ks++) {
            const int kb = ks * 8;
            uint32_t af[4][4];
#pragma unroll
            for (int mt = 0; mt < 4; mt++) {
                const uint32_t* ar0 = Ac + (wm + mt * 16 + g) * AST + kb;
                const uint32_t* ar1 = ar0 + 8 * AST;
                af[mt][0] = ar0[tig];
                af[mt][1] = ar1[tig];
                af[mt][2] = ar0[tig + 4];
                af[mt][3] = ar1[tig + 4];
            }
            uint32_t bf[8][2];
#pragma unroll
            for (int nt = 0; nt < 8; nt++) {
                const int nb2 = wn + nt * 8 + g;
                bf[nt][0] = Bc[(kb + tig    ) * BST + nb2];
                bf[nt][1] = Bc[(kb + tig + 4) * BST + nb2];
            }
#pragma unroll
            for (int mt = 0; mt < 4; mt++)
#pragma unroll
                for (int nt = 0; nt < 8; nt++)
                    mma_tf32(acc[mt][nt], af[mt], bf[nt]);
        }
        cur++;
        if (cur >= 3) cur -= 3;
    }

    // ---- epilogue ----
#pragma unroll
    for (int mt = 0; mt < 4; mt++) {
        const int r0 = bm + wm + mt * 16 + g;
        const int r1 = r0 + 8;
#pragma unroll
        for (int nt = 0; nt < 8; nt++) {
            const int col = bn + wn + nt * 8 + tig * 2;
            float2 bv = *(const float2*)(bias + col);
            float2 v0, v1;
            v0.x = acc[mt][nt][0] + bv.x;
            v0.y = acc[mt][nt][1] + bv.y;
            v1.x = acc[mt][nt][2] + bv.x;
            v1.y = acc[mt][nt][3] + bv.y;
            if (EPI == 1) {
                float2 ra = *(const float2*)(res + (size_t)r0 * N + col);
                float2 rb = *(const float2*)(res + (size_t)r1 * N + col);
                v0.x += ra.x; v0.y += ra.y;
                v1.x += rb.x; v1.y += rb.y;
            }
            if (EPI == 2) {
                v0.x = 0.5f * v0.x * (1.0f + erff(v0.x * 0.70710678118654752f));
                v0.y = 0.5f * v0.y * (1.0f + erff(v0.y * 0.70710678118654752f));
                v1.x = 0.5f * v1.x * (1.0f + erff(v1.x * 0.70710678118654752f));
                v1.y = 0.5f * v1.y * (1.0f + erff(v1.y * 0.70710678118654752f));
            }
            *(float2*)(C + (size_t)r0 * N + col) = v0;
            *(float2*)(C + (size_t)r1 * N + col) = v1;
        }
    }
}

template <int EPI>
__global__ void __launch_bounds__(128)
gemm_tf32_kernel(const float* __restrict__ A, const float* __restrict__ W,
                 const float* __restrict__ bias, const float* __restrict__ res,
                 float* __restrict__ C, int M, int N, int K)
{
    extern __shared__ uint32_t smg[];
    gemm_body<EPI>(A, W, bias, res, C, M, N, K,
                   blockIdx.y * 128, blockIdx.x * 128, smg);
}

// Fused QKV projection: grid.x = 24 (3 matrices x 8 col-blocks)
__global__ void __launch_bounds__(128)
gemm_qkv_kernel(const float* __restrict__ x,
                const float* __restrict__ wq, const float* __restrict__ bq, float* q,
                const float* __restrict__ wk, const float* __restrict__ bk, float* k,
                const float* __restrict__ wv, const float* __restrict__ bv, float* v)
{
    extern __shared__ uint32_t smg[];
    const int which = blockIdx.x >> 3;
    const int bn    = (blockIdx.x & 7) * 128;
    const float* W  = (which == 0) ? wq : (which == 1) ? wk : wv;
    const float* B  = (which == 0) ? bq : (which == 1) ? bk : bv;
    float*       C  = (which == 0) ? q  : (which == 1) ? k  : v;
    gemm_body<0>(x, W, B, nullptr, C, MROWS, D_MODEL, D_MODEL,
                 blockIdx.y * 128, bn, smg);
}

// ---------------------------------------------------------------------------
// Tensor-core flash attention (R7-validated, unchanged).
// BQ=128, BK=64, HD=64. 128 threads = 4 warps; each warp owns 32 q rows.
// ---------------------------------------------------------------------------
#define AS 68
#define ATTN_SMEM ((64 * AS + 64 * AS + 128 * AS) * 4 + 64 * 4)
#define NT (SEQ / 64)

__global__ void __launch_bounds__(128)
attn_mma_kernel(const float* __restrict__ q, const float* __restrict__ k,
                const float* __restrict__ v, const int* __restrict__ mask,
                float* __restrict__ ctx)
{
    extern __shared__ uint32_t sm[];
    uint32_t* Ks = sm;
    uint32_t* Vs = Ks + 64 * AS;
    uint32_t* Ps = Vs + 64 * AS;
    int*      Ms = (int*)(Ps + 128 * AS);

    const int tid  = threadIdx.x;
    const int lane = tid & 31;
    const int wid  = tid >> 5;
    const int g    = lane >> 2;
    const int tig  = lane & 3;
    const int b    = blockIdx.y >> 4;
    const int h    = blockIdx.y & 15;
    const int m0   = b * SEQ + blockIdx.x * 128;
    const size_t colh = (size_t)h * HDIM;
    uint32_t* Pw  = Ps + wid * 32 * AS;
    const int wq0 = wid * 32;
    const float SCL2 = 0.125f * 1.44269504088896340736f;

#pragma unroll
    for (int it = 0; it < 16; it++) {
        int c = tid + it * 128;
        int r = c >> 4, c4 = (c & 15) * 4;
        cp16(Ps + r * AS + c4, q + (size_t)(m0 + r) * D_MODEL + colh + c4);
    }
#pragma unroll
    for (int it = 0; it < 8; it++) {
        int c = tid + it * 128;
        int r = c >> 4, c4 = (c & 15) * 4;
        cp16(Ks + r * AS + c4, k + (size_t)(b * SEQ + r) * D_MODEL + colh + c4);
    }
    cp_commit();
#pragma unroll
    for (int it = 0; it < 8; it++) {
        int c = tid + it * 128;
        int r = c >> 4, c4 = (c & 15) * 4;
        cp16(Vs + r * AS + c4, v + (size_t)(b * SEQ + r) * D_MODEL + colh + c4);
    }
    cp_commit();
    if (tid < 64) Ms[tid] = mask[b * SEQ + tid];

    cp_wait<1>();
    __syncthreads();

    uint32_t qf[2][8][4];
#pragma unroll
    for (int mt = 0; mt < 2; mt++)
#pragma unroll
        for (int ks = 0; ks < 8; ks++) {
            const uint32_t* r0 = Ps + (wq0 + mt * 16 + g) * AS + ks * 8;
            const uint32_t* r1 = r0 + 8 * AS;
            qf[mt][ks][0] = r0[tig];
            qf[mt][ks][1] = r1[tig];
            qf[mt][ks][2] = r0[tig + 4];
            qf[mt][ks][3] = r1[tig + 4];
        }
    __syncthreads();

    float m_i[2][2], l_i[2][2];
#pragma unroll
    for (int mt = 0; mt < 2; mt++) {
        m_i[mt][0] = -3.0e38f; m_i[mt][1] = -3.0e38f;
        l_i[mt][0] = 0.0f;     l_i[mt][1] = 0.0f;
    }
    float of[2][8][4];
#pragma unroll
    for (int mt = 0; mt < 2; mt++)
#pragma unroll
        for (int nt = 0; nt < 8; nt++)
#pragma unroll
            for (int r = 0; r < 4; r++) of[mt][nt][r] = 0.0f;

    for (int kt = 0; kt < NT; kt++) {
        const bool more = (kt + 1 < NT);
        const int n1 = b * SEQ + (kt + 1) * 64;

#pragma unroll
        for (int half = 0; half < 2; half++) {
            float sc[2][4][4];
#pragma unroll
            for (int mt = 0; mt < 2; mt++)
#pragma unroll
                for (int n = 0; n < 4; n++)
#pragma unroll
                    for (int r = 0; r < 4; r++) sc[mt][n][r] = 0.0f;

#pragma unroll
            for (int ks = 0; ks < 8; ks++) {
                uint32_t bf[4][2];
#pragma unroll
                for (int n = 0; n < 4; n++) {
                    const uint32_t* kr = Ks + (half * 32 + n * 8 + g) * AS + ks * 8;
                    bf[n][0] = kr[tig];
                    bf[n][1] = kr[tig + 4];
                }
#pragma unroll
                for (int mt = 0; mt < 2; mt++)
#pragma unroll
                    for (int n = 0; n < 4; n++)
                        mma_tf32(sc[mt][n], qf[mt][ks], bf[n]);
            }

#pragma unroll
            for (int n = 0; n < 4; n++) {
                int c0 = half * 32 + n * 8 + 2 * tig;
                if (Ms[c0] == 0) {
#pragma unroll
                    for (int mt = 0; mt < 2; mt++) { sc[mt][n][0] = -1e9f; sc[mt][n][2] = -1e9f; }
                }
                if (Ms[c0 + 1] == 0) {
#pragma unroll
                    for (int mt = 0; mt < 2; mt++) { sc[mt][n][1] = -1e9f; sc[mt][n][3] = -1e9f; }
                }
            }

#pragma unroll
            for (int mt = 0; mt < 2; mt++) {
#pragma unroll
                for (int hh = 0; hh < 2; hh++) {
                    const int i0  = hh * 2;
                    const int row = mt * 16 + (hh ? (g + 8) : g);
                    float tm = -3.0e38f;
#pragma unroll
                    for (int n = 0; n < 4; n++)
                        tm = fmaxf(tm, fmaxf(sc[mt][n][i0], sc[mt][n][i0 + 1]));
                    tm = fmaxf(tm, __shfl_xor_sync(0xffffffffu, tm, 1));
                    tm = fmaxf(tm, __shfl_xor_sync(0xffffffffu, tm, 2));
                    if (tm > m_i[mt][hh]) {
                        float corr = fexp2((m_i[mt][hh] - tm) * SCL2);
                        m_i[mt][hh] = tm;
                        l_i[mt][hh] *= corr;
#pragma unroll
                        for (int nt = 0; nt < 8; nt++) {
                            of[mt][nt][i0]     *= corr;
                            of[mt][nt][i0 + 1] *= corr;
                        }
                    }
                    const float nm = m_i[mt][hh];
                    float rs = 0.0f;
#pragma unroll
                    for (int n = 0; n < 4; n++) {
                        float p0 = fexp2((sc[mt][n][i0]     - nm) * SCL2);
                        float p1 = fexp2((sc[mt][n][i0 + 1] - nm) * SCL2);
                        rs += p0 + p1;
                        Pw[row * AS + half * 32 + n * 8 + 2 * tig    ] = __float_as_uint(p0);
                        Pw[row * AS + half * 32 + n * 8 + 2 * tig + 1] = __float_as_uint(p1);
                    }
                    rs += __shfl_xor_sync(0xffffffffu, rs, 1);
                    rs += __shfl_xor_sync(0xffffffffu, rs, 2);
                    l_i[mt][hh] += rs;
                }
            }
        }
        __syncwarp();

        __syncthreads();

        if (more) {
#pragma unroll
            for (int it = 0; it < 8; it++) {
                int c = tid + it * 128;
                int r = c >> 4, c4 = (c & 15) * 4;
                cp16(Ks + r * AS + c4, k + (size_t)(n1 + r) * D_MODEL + colh + c4);
            }
            cp_commit();
            if (tid < 64) Ms[tid] = mask[n1 + tid];
        }

        if (more) cp_wait<1>(); else cp_wait<0>();
        __syncthreads();

#pragma unroll
        for (int ks = 0; ks < 8; ks++) {
            uint32_t bfv[8][2];
#pragma unroll
            for (int nt = 0; nt < 8; nt++) {
                bfv[nt][0] = Vs[(ks * 8 + tig    ) * AS + nt * 8 + g];
                bfv[nt][1] = Vs[(ks * 8 + tig + 4) * AS + nt * 8 + g];
            }
#pragma unroll
            for (int mt = 0; mt < 2; mt++) {
                uint32_t af[4];
                const uint32_t* p0p = Pw + (mt * 16 + g) * AS + ks * 8;
                const uint32_t* p1p = p0p + 8 * AS;
                af[0] = p0p[tig];
                af[1] = p1p[tig];
                af[2] = p0p[tig + 4];
                af[3] = p1p[tig + 4];
#pragma unroll
                for (int nt = 0; nt < 8; nt++)
                    mma_tf32(of[mt][nt], af, bfv[nt]);
            }
        }

        cp_wait<0>();
        __syncthreads();
        if (more) {
#pragma unroll
            for (int it = 0; it < 8; it++) {
                int c = tid + it * 128;
                int r = c >> 4, c4 = (c & 15) * 4;
                cp16(Vs + r * AS + c4, v + (size_t)(n1 + r) * D_MODEL + colh + c4);
            }
            cp_commit();
        }
    }

#pragma unroll
    for (int mt = 0; mt < 2; mt++) {
        const float inv0 = 1.0f / l_i[mt][0];
        const float inv1 = 1.0f / l_i[mt][1];
        const int r0 = m0 + wq0 + mt * 16 + g;
        const int r1 = r0 + 8;
#pragma unroll
        for (int nt = 0; nt < 8; nt++) {
            const size_t col = colh + nt * 8 + 2 * tig;
            float2 v0 = { of[mt][nt][0] * inv0, of[mt][nt][1] * inv0 };
            float2 v1 = { of[mt][nt][2] * inv1, of[mt][nt][3] * inv1 };
            *(float2*)(ctx + (size_t)r0 * D_MODEL + col) = v0;
            *(float2*)(ctx + (size_t)r1 * D_MODEL + col) = v1;
        }
    }
}

// ---------------------------------------------------------------------------
// LayerNorm kernels (unchanged)
// ---------------------------------------------------------------------------
__device__ __forceinline__ float block_reduce_sum(float val, float* red)
{
#pragma unroll
    for (int o = 16; o > 0; o >>= 1)
        val += __shfl_xor_sync(0xffffffffu, val, o);
    int warp = threadIdx.x >> 5;
    if ((threadIdx.x & 31) == 0) red[warp] = val;
    __syncthreads();
    if (threadIdx.x < 32) {
        float v = (threadIdx.x < 8) ? red[threadIdx.x] : 0.0f;
#pragma unroll
        for (int o = 4; o > 0; o >>= 1)
            v += __shfl_xor_sync(0xffffffffu, v, o);
        if (threadIdx.x == 0) red[0] = v;
    }
    __syncthreads();
    float r = red[0];
    __syncthreads();
    return r;
}

__global__ void __launch_bounds__(256)
ln_kernel(const float* __restrict__ in, const float* __restrict__ g,
          const float* __restrict__ bb, float eps, float* __restrict__ out)
{
    __shared__ float red[8];
    const int row = blockIdx.x;
    const float* rp = in + (size_t)row * D_MODEL;
    float vloc[4];
    float s = 0.0f;
#pragma unroll
    for (int i = 0; i < 4; i++) {
        vloc[i] = rp[threadIdx.x + i * 256];
        s += vloc[i];
    }
    float mean = block_reduce_sum(s, red) * (1.0f / D_MODEL);
    float vs = 0.0f;
#pragma unroll
    for (int i = 0; i < 4; i++) {
        float dv = vloc[i] - mean;
        vs += dv * dv;
    }
    float var  = block_reduce_sum(vs, red) * (1.0f / D_MODEL);
    float rstd = rsqrtf(var + eps);
#pragma unroll
    for (int i = 0; i < 4; i++) {
        int c = threadIdx.x + i * 256;
        out[(size_t)row * D_MODEL + c] = (vloc[i] - mean) * rstd * g[c] + bb[c];
    }
}

__global__ void __launch_bounds__(256)
ln2_fuse_kernel(const float* __restrict__ t2, const float* __restrict__ x1,
                const float* __restrict__ lnf_g, const float* __restrict__ lnf_b,
                const float* __restrict__ ln2_g, const float* __restrict__ ln2_b,
                float* __restrict__ out)
{
    __shared__ float red[8];
    const int row = blockIdx.x;
    const float* tp = t2 + (size_t)row * D_MODEL;
    const float* xp = x1 + (size_t)row * D_MODEL;
    float tv[4], xv[4];
    float s = 0.0f;
#pragma unroll
    for (int i = 0; i < 4; i++) {
        int c = threadIdx.x + i * 256;
        tv[i] = tp[c];
        xv[i] = xp[c];
        s += tv[i];
    }
    float mean1 = block_reduce_sum(s, red) * (1.0f / D_MODEL);
    float vs = 0.0f;
#pragma unroll
    for (int i = 0; i < 4; i++) {
        float dv = tv[i] - mean1;
        vs += dv * dv;
    }
    float var1  = block_reduce_sum(vs, red) * (1.0f / D_MODEL);
    float rstd1 = rsqrtf(var1 + 1e-12f);

    float u[4];
    float s2 = 0.0f;
#pragma unroll
    for (int i = 0; i < 4; i++) {
        int c = threadIdx.x + i * 256;
        float ff = (tv[i] - mean1) * rstd1 * lnf_g[c] + lnf_b[c];
        u[i] = xv[i] + ff;
        s2 += u[i];
    }
    float mean2 = block_reduce_sum(s2, red) * (1.0f / D_MODEL);
    float vs2 = 0.0f;
#pragma unroll
    for (int i = 0; i < 4; i++) {
        float dv = u[i] - mean2;
        vs2 += dv * dv;
    }
    float var2  = block_reduce_sum(vs2, red) * (1.0f / D_MODEL);
    float rstd2 = rsqrtf(var2 + 1e-5f);
#pragma unroll
    for (int i = 0; i < 4; i++) {
        int c = threadIdx.x + i * 256;
        out[(size_t)row * D_MODEL + c] = (u[i] - mean2) * rstd2 * ln2_g[c] + ln2_b[c];
    }
}

// ---------------------------------------------------------------------------
// Launcher
// ---------------------------------------------------------------------------
extern "C" void kernel_launch(void* const* d_in, const int* in_sizes, int n_in,
                              void* d_out, int out_size)
{
    const float* x      = (const float*)d_in[0];
    const int*   mask   = (const int*)  d_in[1];
    const float* wq     = (const float*)d_in[2];
    const float* bq     = (const float*)d_in[3];
    const float* wk     = (const float*)d_in[4];
    const float* bk     = (const float*)d_in[5];
    const float* wv     = (const float*)d_in[6];
    const float* bv     = (const float*)d_in[7];
    const float* wo     = (const float*)d_in[8];
    const float* bo     = (const float*)d_in[9];
    const float* ln1_g  = (const float*)d_in[10];
    const float* ln1_b  = (const float*)d_in[11];
    const float* w1     = (const float*)d_in[12];
    const float* b1     = (const float*)d_in[13];
    const float* w2     = (const float*)d_in[14];
    const float* b2     = (const float*)d_in[15];
    const float* lnf_g  = (const float*)d_in[16];
    const float* lnf_b  = (const float*)d_in[17];
    const float* ln2_g  = (const float*)d_in[18];
    const float* ln2_b  = (const float*)d_in[19];
    float* out = (float*)d_out;

    float *q, *k, *v, *ctx, *t, *x1, *h;
    cudaGetSymbolAddress((void**)&q,   g_q);
    cudaGetSymbolAddress((void**)&k,   g_k);
    cudaGetSymbolAddress((void**)&v,   g_v);
    cudaGetSymbolAddress((void**)&ctx, g_ctx);
    cudaGetSymbolAddress((void**)&t,   g_t);
    cudaGetSymbolAddress((void**)&x1,  g_x1);
    cudaGetSymbolAddress((void**)&h,   g_h);

    cudaFuncSetAttribute(gemm_qkv_kernel,
                         cudaFuncAttributeMaxDynamicSharedMemorySize, GEMM_SMEM);
    cudaFuncSetAttribute(gemm_tf32_kernel<1>,
                         cudaFuncAttributeMaxDynamicSharedMemorySize, GEMM_SMEM);
    cudaFuncSetAttribute(gemm_tf32_kernel<2>,
                         cudaFuncAttributeMaxDynamicSharedMemorySize, GEMM_SMEM);
    cudaFuncSetAttribute(attn_mma_kernel,
                         cudaFuncAttributeMaxDynamicSharedMemorySize, ATTN_SMEM);

    // fused QKV projections
    gemm_qkv_kernel<<<dim3(24, MROWS / 128), 128, GEMM_SMEM>>>(
        x, wq, bq, q, wk, bk, k, wv, bv, v);

    // attention
    attn_mma_kernel<<<dim3(SEQ / 128, BATCH * NHEAD), 128, ATTN_SMEM>>>(
        q, k, v, mask, ctx);

    // output projection + residual, then LN1
    gemm_tf32_kernel<1><<<dim3(D_MODEL / 128, MROWS / 128), 128, GEMM_SMEM>>>(
        ctx, wo, bo, x, t, MROWS, D_MODEL, D_MODEL);
    ln_kernel<<<MROWS, 256>>>(t, ln1_g, ln1_b, 1e-5f, x1);

    // FFN
    gemm_tf32_kernel<2><<<dim3(FFDIM / 128, MROWS / 128), 128, GEMM_SMEM>>>(
        x1, w1, b1, nullptr, h, MROWS, FFDIM, D_MODEL);
    gemm_tf32_kernel<1><<<dim3(D_MODEL / 128, MROWS / 128), 128, GEMM_SMEM>>>(
        h, w2, b2, x1, t, MROWS, D_MODEL, FFDIM);

    // fused double LayerNorm epilogue
    ln2_fuse_kernel<<<MROWS, 256>>>(t, x1, lnf_g, lnf_b, ln2_g, ln2_b, out);
}